// round 12
// baseline (speedup 1.0000x reference)
#include <cuda_runtime.h>
#include <cuda_bf16.h>
#include <math.h>
#include <stdint.h>

#define B_    16
#define C_    256
#define N_    1024      // 32*32 tokens
#define NH_   8
#define HD_   32
#define HALF_ 128
#define BH_   (B_*NH_)  // 128
#define TABN_ 3969      // 63*63

typedef unsigned long long u64;
typedef unsigned int u32;

// bf16 mma m16n8k16, fp32 accum
#define MMA16816(d0,d1,d2,d3,a0,a1,a2,a3,b0,b1) \
    asm("mma.sync.aligned.m16n8k16.row.col.f32.bf16.bf16.f32 " \
        "{%0,%1,%2,%3}, {%4,%5,%6,%7}, {%8,%9}, {%0,%1,%2,%3};" \
        : "+f"(d0), "+f"(d1), "+f"(d2), "+f"(d3) \
        : "r"(a0), "r"(a1), "r"(a2), "r"(a3), "r"(b0), "r"(b1))

#define LDSM_X4(r0,r1,r2,r3,addr) \
    asm volatile("ldmatrix.sync.aligned.m8n8.x4.shared.b16 {%0,%1,%2,%3}, [%4];" \
        : "=r"(r0), "=r"(r1), "=r"(r2), "=r"(r3) : "r"(addr))

#define LDSM_X4_T(r0,r1,r2,r3,addr) \
    asm volatile("ldmatrix.sync.aligned.m8n8.x4.trans.shared.b16 {%0,%1,%2,%3}, [%4];" \
        : "=r"(r0), "=r"(r1), "=r"(r2), "=r"(r3) : "r"(addr))

#define CP_ASYNC16(dst,src) \
    asm volatile("cp.async.cg.shared.global [%0], [%1], 16;" :: "r"(dst), "l"(src))
#define CP_COMMIT() asm volatile("cp.async.commit_group;")
#define CP_WAIT0()  asm volatile("cp.async.wait_group 0;")

__device__ __forceinline__ u32 smem_u32(const void* p) {
    u32 a;
    asm("{ .reg .u64 t; cvta.to.shared.u64 t, %1; cvt.u32.u64 %0, t; }"
        : "=r"(a) : "l"(p));
    return a;
}

// ---- scratch (device globals; no runtime allocation allowed) ----
__device__ float g_q[B_*C_*N_];             // 16 MB, [b][c][tok]
__device__ float g_k[B_*C_*N_];             // 16 MB
__device__ u32 g_wfrag[8*8*24*32*4];        // pre-swizzled A-fragments (qkv+proj)
__device__ __nv_bfloat16 g_qs[BH_*N_*96];   // [qh|ql|qh]  25 MB
__device__ __nv_bfloat16 g_ks[BH_*N_*96];   // [kh|kh|kl]  25 MB
__device__ __nv_bfloat16 g_vt[BH_*64*N_];   // [bh][vh|vl][key] 16 MB
__device__ float g_o[BH_*N_*HD_];           // 16 MB
__device__ __nv_bfloat16 g_osh[B_*C_*N_];   // attn out, high split, [b][c][tok]
__device__ __nv_bfloat16 g_osl[B_*C_*N_];   // low split
__device__ float g_tab[TABN_*NH_];
__device__ float g_biasB[NH_*N_*N_];        // 32 MB, [h][query][key], pre-scaled

__device__ __forceinline__ u32 pkh(__nv_bfloat16 a, __nv_bfloat16 b) {
    __nv_bfloat162 t; t.x = a; t.y = b;
    return *(u32*)&t;
}
__device__ __forceinline__ u32 pkf(float a, float b) {
    __nv_bfloat162 t = __floats2bfloat162_rn(a, b);
    return *(u32*)&t;
}
// split (v0,v1) into packed bf16x2 high + low words (low lane = v0)
__device__ __forceinline__ void split2(float v0, float v1, u32& hw, u32& lw) {
    asm("cvt.rn.bf16x2.f32 %0, %1, %2;" : "=r"(hw) : "f"(v1), "f"(v0));
    float h0 = __uint_as_float(hw << 16);
    float h1 = __uint_as_float(hw & 0xffff0000u);
    float l0 = v0 - h0, l1 = v1 - h1;
    asm("cvt.rn.bf16x2.f32 %0, %1, %2;" : "=r"(lw) : "f"(l1), "f"(l0));
}

// ============================================================
// K_wext: pre-swizzled split-weight A-fragments, K-ext [wh|wl|wh].
// (launch index 0)
// ============================================================
__global__ void __launch_bounds__(256) wext_kernel(
    const float* __restrict__ q1w, const float* __restrict__ q2w,
    const float* __restrict__ k1w, const float* __restrict__ k2w,
    const float* __restrict__ v1w, const float* __restrict__ v2w,
    const float* __restrict__ p1w, const float* __restrict__ p2w)
{
    const float* Ws[8] = {q1w, q2w, k1w, k2w, v1w, v2w, p1w, p2w};
    int id = blockIdx.x * 256 + threadIdx.x;   // 0..196607
    int j    = id & 3;
    int lane = (id >> 2) & 31;
    int ks   = (id >> 7) % 24;
    int rbm  = id / (128 * 24);
    int rb = rbm & 7, m = rbm >> 3;
    int row = rb * 16 + (lane >> 2) + (j & 1) * 8;
    int col = ks * 16 + 2 * (lane & 3) + ((j >> 1) & 1) * 8;
    int region = col >> 7, ic = col & 127;
    const float* W = Ws[m];
    float v0 = W[row * 128 + ic], v1 = W[row * 128 + ic + 1];
    u32 r;
    if (region == 1) {
        __nv_bfloat16 h0 = __float2bfloat16(v0), h1 = __float2bfloat16(v1);
        r = pkf(v0 - __bfloat162float(h0), v1 - __bfloat162float(h1));
    } else {
        r = pkh(__float2bfloat16(v0), __float2bfloat16(v1));
    }
    g_wfrag[id] = r;
}

// ============================================================
// K2: CPB table MLP (launch index 1)
// ============================================================
__global__ void __launch_bounds__(256) tab_kernel(
    const float* __restrict__ w1, const float* __restrict__ b1,
    const float* __restrict__ w2)
{
    __shared__ float w1s[256];
    __shared__ float b1s[128];
    __shared__ float w2s[1024];
    int tid = threadIdx.x;
    if (tid < 256) w1s[tid] = w1[tid];
    if (tid < 128) b1s[tid] = b1[tid];
    for (int i = tid; i < 1024; i += 256) w2s[i] = w2[i];
    __syncthreads();

    int p = blockIdx.x * 256 + tid;
    if (p >= TABN_) return;
    int a = p / 63, b = p % 63;
    float t0 = ((float)(a - 31) / 31.0f) * 3.2f;
    float t1 = ((float)(b - 31) / 31.0f) * 3.2f;
    t0 = copysignf(1.f - __expf(-fabsf(t0)), t0);
    t1 = copysignf(1.f - __expf(-fabsf(t1)), t1);

    float acc[NH_];
    #pragma unroll
    for (int h = 0; h < NH_; h++) acc[h] = 0.f;
    for (int k = 0; k < 128; k++) {
        float hv = fmaxf(w1s[2 * k] * t0 + w1s[2 * k + 1] * t1 + b1s[k], 0.f);
        #pragma unroll
        for (int h = 0; h < NH_; h++) acc[h] += w2s[h * 128 + k] * hv;
    }
    #pragma unroll
    for (int h = 0; h < NH_; h++) g_tab[p * NH_ + h] = acc[h];
}

// ============================================================
// K3: expand bias, pre-scaled (bias - M_h)*log2e. (launch index 2)
// ============================================================
__global__ void __launch_bounds__(256) bias_kernel(const float* __restrict__ ls)
{
    __shared__ float mh[NH_];
    if (threadIdx.x < NH_)
        mh[threadIdx.x] = __expf(fminf(ls[threadIdx.x], 4.6051702f)) + 16.f;
    __syncthreads();

    int n = blockIdx.x;                       // query
    int m = blockIdx.y * 256 + threadIdx.x;   // key
    int i = n >> 5, j = n & 31;
    int p = m >> 5, q = m & 31;
    int idx = (i - p + 31) * 63 + (j - q + 31);
    const float* t = g_tab + idx * NH_;
    #pragma unroll
    for (int h = 0; h < NH_; h++) {
        float v = 16.f / (1.f + __expf(-t[h]));
        g_biasB[((size_t)h * N_ + n) * N_ + m] = (v - mh[h]) * 1.44269504f;
    }
}

// ============================================================
// K_qkvgemm: 32-token tiles (512 blocks), coalesced A-fragments,
// v-splits staged through smem for coalesced uint4 stores.
// (launch index 3 — ncu slot)
// ============================================================
__global__ void __launch_bounds__(256) qkvgemm_kernel(
    const float* __restrict__ x,
    const float* __restrict__ q1b, const float* __restrict__ q2b,
    const float* __restrict__ k1b, const float* __restrict__ k2b,
    const float* __restrict__ v1b, const float* __restrict__ v2b)
{
    __shared__ __align__(16) __nv_bfloat16 xh_s[128][40];   // [ch][tok], pad 40
    __shared__ __align__(16) __nv_bfloat16 xl_s[128][40];

    const int tid  = threadIdx.x;
    const int lane = tid & 31;
    const int w    = tid >> 5;
    const int b    = blockIdx.y;
    const int tok0 = blockIdx.x * 32;
    const int r0   = w * 16 + (lane >> 2);
    const int fc2  = 2 * (lane & 3);

    const u32 xh0 = smem_u32(&xh_s[0][0]);
    const u32 xl0 = smem_u32(&xl_s[0][0]);
    // ldmatrix x4.trans lane offset for 80-byte rows
    const u32 lmoff = (u32)((((lane & 7) + ((lane >> 3) & 1) * 8) * 80)
                            + ((lane >> 4) & 1) * 16);

    const float* Bss[6] = {q1b, q2b, k1b, k2b, v1b, v2b};

    for (int half = 0; half < 2; half++) {
        __syncthreads();
        // stage x half as bf16 splits: 128 ch x 32 tok
        #pragma unroll
        for (int r = 0; r < 4; r++) {
            int idx = r * 256 + tid;             // 0..1023
            int ch = idx >> 3, t4 = (idx & 7) * 4;
            float4 xv = *(const float4*)&x[((size_t)(b * 256 + half * 128 + ch) << 10) + tok0 + t4];
            u32 hw0, lw0, hw1, lw1;
            split2(xv.x, xv.y, hw0, lw0);
            split2(xv.z, xv.w, hw1, lw1);
            *(uint2*)&xh_s[ch][t4] = make_uint2(hw0, hw1);
            *(uint2*)&xl_s[ch][t4] = make_uint2(lw0, lw1);
        }
        __syncthreads();

        for (int g = 0; g < 3; g++) {
            const int m = g * 2 + half;
            const uint4* wf = (const uint4*)g_wfrag + ((size_t)(m * 8 + w) * 24) * 32 + lane;

            float c[4][4];
            #pragma unroll
            for (int i = 0; i < 4; i++) { c[i][0] = c[i][1] = c[i][2] = c[i][3] = 0.f; }

            uint4 aa = __ldg(&wf[0]);
            #pragma unroll 4
            for (int ks = 0; ks < 24; ks++) {
                uint4 nxt = aa;
                if (ks < 23) nxt = __ldg(&wf[(ks + 1) * 32]);
                u32 bb = ((ks < 16) ? xh0 : xl0) + (u32)((ks & 7) * 16 * 80) + lmoff;
                #pragma unroll
                for (int nt = 0; nt < 2; nt++) {
                    u32 f0, f1, f2, f3;
                    LDSM_X4_T(f0, f1, f2, f3, bb + nt * 32);
                    MMA16816(c[2*nt][0], c[2*nt][1], c[2*nt][2], c[2*nt][3],
                             aa.x, aa.y, aa.z, aa.w, f0, f1);
                    MMA16816(c[2*nt+1][0], c[2*nt+1][1], c[2*nt+1][2], c[2*nt+1][3],
                             aa.x, aa.y, aa.z, aa.w, f2, f3);
                }
                aa = nxt;
            }

            float bb0 = __ldg(&Bss[m][r0]);
            float bb1 = __ldg(&Bss[m][r0 + 8]);
            const float* xr = x + ((size_t)(b * 256 + half * 128) << 10);

            if (g < 2) {
                float* op = (g == 0 ? g_q : g_k) + ((size_t)(b * 256 + half * 128) << 10);
                #pragma unroll
                for (int n8 = 0; n8 < 4; n8++) {
                    int tok = tok0 + n8 * 8 + fc2;
                    float2 rx0 = *(const float2*)&xr[((size_t)r0 << 10) + tok];
                    float2 rx1 = *(const float2*)&xr[((size_t)(r0 + 8) << 10) + tok];
                    float2 o0 = make_float2(c[n8][0] + rx0.x + bb0, c[n8][1] + rx0.y + bb0);
                    float2 o1 = make_float2(c[n8][2] + rx1.x + bb1, c[n8][3] + rx1.y + bb1);
                    *(float2*)&op[((size_t)r0 << 10) + tok] = o0;
                    *(float2*)&op[((size_t)(r0 + 8) << 10) + tok] = o1;
                }
            } else {
                // v: stage splits into xh_s/xl_s (B-operands done), then
                // block-coalesced uint4 stores to g_vt.
                __syncthreads();
                #pragma unroll
                for (int n8 = 0; n8 < 4; n8++) {
                    int tokl = n8 * 8 + fc2;
                    int tok = tok0 + tokl;
                    float2 rx0 = *(const float2*)&xr[((size_t)r0 << 10) + tok];
                    float2 rx1 = *(const float2*)&xr[((size_t)(r0 + 8) << 10) + tok];
                    float v00 = c[n8][0] + rx0.x + bb0, v01 = c[n8][1] + rx0.y + bb0;
                    float v10 = c[n8][2] + rx1.x + bb1, v11 = c[n8][3] + rx1.y + bb1;
                    u32 hw, lw;
                    split2(v00, v01, hw, lw);
                    *(u32*)&xh_s[r0][tokl] = hw; *(u32*)&xl_s[r0][tokl] = lw;
                    split2(v10, v11, hw, lw);
                    *(u32*)&xh_s[r0 + 8][tokl] = hw; *(u32*)&xl_s[r0 + 8][tokl] = lw;
                }
                __syncthreads();
                #pragma unroll
                for (int r = 0; r < 4; r++) {
                    int idx = r * 256 + tid;         // 0..1023
                    int s   = idx >> 9;              // 0=h, 1=l
                    int ch  = (idx >> 2) & 127;
                    int seg = idx & 3;
                    int c0 = half * 128 + ch;
                    int hh_ = c0 >> 5, dd_ = c0 & 31;
                    uint4 v = *(const uint4*)(s ? &xl_s[ch][seg * 8] : &xh_s[ch][seg * 8]);
                    *(uint4*)&g_vt[(((size_t)(b * 8 + hh_)) * 64 + s * 32 + dd_) * 1024
                                   + tok0 + seg * 8] = v;
                }
            }
        }
    }
}

// ============================================================
// K_normsplit (launch index 4)
// ============================================================
__global__ void __launch_bounds__(128) normsplit_kernel()
{
    __shared__ float xs[32][129];
    __shared__ u32 os[128][49];

    const int tid = threadIdx.x;
    const int chunk = blockIdx.x, bh = blockIdx.y, qk = blockIdx.z;
    const int b = bh >> 3, h = bh & 7;
    const int tok0 = chunk * 128;
    const float* src = (qk ? g_k : g_q) + ((size_t)(b * 256 + h * 32) << 10) + tok0;

    #pragma unroll
    for (int r = 0; r < 8; r++) {
        int idx = r * 128 + tid;
        int ch = idx >> 5, t4 = (idx & 31) * 4;
        float4 v = *(const float4*)&src[((size_t)ch << 10) + t4];
        xs[ch][t4] = v.x; xs[ch][t4+1] = v.y; xs[ch][t4+2] = v.z; xs[ch][t4+3] = v.w;
    }
    __syncthreads();

    float vals[32]; float s = 0.f;
    #pragma unroll
    for (int ch = 0; ch < 32; ch++) { vals[ch] = xs[ch][tid]; s += vals[ch] * vals[ch]; }
    float inv = 1.f / fmaxf(sqrtf(s), 1e-12f);

    #pragma unroll
    for (int j = 0; j < 16; j++) {
        float v0 = vals[2*j] * inv, v1 = vals[2*j+1] * inv;
        u32 hh, ll;
        split2(v0, v1, hh, ll);
        if (qk == 0) { os[tid][j] = hh; os[tid][16+j] = ll; os[tid][32+j] = hh; }
        else         { os[tid][j] = hh; os[tid][16+j] = hh; os[tid][32+j] = ll; }
    }
    __syncthreads();

    __nv_bfloat16* dst = (qk ? g_ks : g_qs) + ((size_t)bh * N_ + tok0) * 96;
    #pragma unroll
    for (int r = 0; r < 12; r++) {
        int idx = r * 128 + tid;
        int row = idx / 12, seg = idx % 12;
        uint4 v = make_uint4(os[row][seg*4], os[row][seg*4+1],
                             os[row][seg*4+2], os[row][seg*4+3]);
        *(uint4*)(dst + (size_t)row * 96 + seg * 8) = v;
    }
}

// ============================================================
// K4: attention — chunked softmax, 3 CTAs/SM, deduped aQ.
// (launch index 5)
// ============================================================
__global__ void __launch_bounds__(256, 3) attn_kernel(const float* __restrict__ logit_scale)
{
    __shared__ __align__(16) __nv_bfloat16 ks_s[2][64][104];
    __shared__ __align__(16) __nv_bfloat16 vt_s[2][64][72];

    const int tid  = threadIdx.x;
    const int lane = tid & 31;
    const int w    = tid >> 5;
    const int bh   = blockIdx.y;
    const int h    = bh & 7;
    const int q0   = blockIdx.x * 128;
    const int qr   = q0 + w * 16 + (lane >> 2);
    const int fc2  = 2 * (lane & 3);

    // K-ext layout is [qh|ql|qh]: ksteps 4,5 duplicate 0,1 -> load 4 only
    u32 aQ[4][4];
    {
        const __nv_bfloat16* qb = g_qs + ((size_t)bh * N_ + qr) * 96;
        #pragma unroll
        for (int ks = 0; ks < 4; ks++) {
            int f = fc2 + 16 * ks;
            aQ[ks][0] = *(const u32*)(qb + f);
            aQ[ks][1] = *(const u32*)(qb + 8 * 96 + f);
            aQ[ks][2] = *(const u32*)(qb + f + 8);
            aQ[ks][3] = *(const u32*)(qb + 8 * 96 + f + 8);
        }
    }

    const float scale = __expf(fminf(logit_scale[h], 4.6051702f));
    const float sl2e  = scale * 1.44269504f;

    float o[4][4];
    #pragma unroll
    for (int i = 0; i < 4; i++)
        #pragma unroll
        for (int j = 0; j < 4; j++) o[i][j] = 0.f;
    float s0 = 0.f, s1 = 0.f;

    const float* bias0 = g_biasB + ((size_t)h * N_ + qr) * N_;
    const float* bias1 = bias0 + (size_t)8 * N_;

    const u32 ks0 = smem_u32(&ks_s[0][0][0]);
    const u32 vt0 = smem_u32(&vt_s[0][0][0]);
    const u32 KSB = 64 * 104 * 2;
    const u32 VTB = 64 * 72 * 2;

    const u32 lmK = (u32)(((((lane >> 4) & 1) * 8 + (lane & 7)) * 104
                           + ((lane >> 3) & 1) * 8) * 2);
    const u32 lmV = (u32)(((((lane >> 4) & 1) * 32 + (lane & 7)) * 72
                           + ((lane >> 3) & 1) * 8) * 2);

    const char* kgbase = (const char*)(g_ks + (size_t)bh * N_ * 96);
    const char* vgbase = (const char*)(g_vt + (size_t)bh * 64 * N_);

    auto stage = [&](int kt, int bf) {
        const char* src = kgbase + (size_t)kt * 64 * 192;
        u32 dst = ks0 + bf * KSB;
        #pragma unroll
        for (int i = 0; i < 3; i++) {
            int idx = i * 256 + tid;
            int key = idx / 12, seg = idx % 12;
            CP_ASYNC16(dst + (key * 104 + seg * 8) * 2, src + key * 192 + seg * 16);
        }
        const char* vs = vgbase + (size_t)kt * 64 * 2;
        u32 vdst = vt0 + bf * VTB;
        #pragma unroll
        for (int i = 0; i < 2; i++) {
            int idx = i * 256 + tid;
            int f = idx / 8, seg = idx % 8;
            CP_ASYNC16(vdst + (f * 72 + seg * 8) * 2, vs + (size_t)f * N_ * 2 + seg * 16);
        }
        CP_COMMIT();
    };

    stage(0, 0);

    for (int kt = 0; kt < 16; kt++) {
        const int buf = kt & 1;
        CP_WAIT0();
        __syncthreads();
        if (kt < 15) stage(kt + 1, buf ^ 1);

        const u32 kbase = ks0 + buf * KSB;
        const u32 vbase = vt0 + buf * VTB;

        #pragma unroll
        for (int kc = 0; kc < 4; kc++) {
            // ---- QK^T for 16 keys ----
            float c[2][4];
            c[0][0] = c[0][1] = c[0][2] = c[0][3] = 0.f;
            c[1][0] = c[1][1] = c[1][2] = c[1][3] = 0.f;
            #pragma unroll
            for (int ks = 0; ks < 6; ks++) {
                const int qi = (ks < 4) ? ks : ks - 4;
                u32 b00, b01, b10, b11;
                LDSM_X4(b00, b01, b10, b11,
                        kbase + lmK + (u32)((kc * 16 * 104 + 16 * ks) * 2));
                MMA16816(c[0][0], c[0][1], c[0][2], c[0][3],
                         aQ[qi][0], aQ[qi][1], aQ[qi][2], aQ[qi][3], b00, b01);
                MMA16816(c[1][0], c[1][1], c[1][2], c[1][3],
                         aQ[qi][0], aQ[qi][1], aQ[qi][2], aQ[qi][3], b10, b11);
            }

            // ---- softmax slice ----
            int kg = kt * 64 + kc * 16 + fc2;
            float2 bb0 = *(const float2*)(bias0 + kg);
            float2 bb1 = *(const float2*)(bias1 + kg);
            float2 bb2 = *(const float2*)(bias0 + kg + 8);
            float2 bb3 = *(const float2*)(bias1 + kg + 8);
            float pv0 = exp2f(fmaf(c[0][0], sl2e, bb0.x));
            float pv1 = exp2f(fmaf(c[0][1], sl2e, bb0.y));
            float pv2 = exp2f(fmaf(c[0][2], sl2e, bb1.x));
            float pv3 = exp2f(fmaf(c[0][3], sl2e, bb1.y));
            float pw0 = exp2f(fmaf(c[1][0], sl2e, bb2.x));
            float pw1 = exp2f(fmaf(c[1][1], sl2e, bb2.y));
            float pw2 = exp2f(fmaf(c[1][2], sl2e, bb3.x));
            float pw3 = exp2f(fmaf(c[1][3], sl2e, bb3.y));
            s0 += (pv0 + pv1) + (pw0 + pw1);
            s1 += (pv2 + pv3) + (pw2 + pw3);

            u32 aPh[4], aPl[4];
            split2(pv0, pv1, aPh[0], aPl[0]);
            split2(pv2, pv3, aPh[1], aPl[1]);
            split2(pw0, pw1, aPh[2], aPl[2]);
            split2(pw2, pw3, aPh[3], aPl[3]);

            // ---- P·V for these 16 keys ----
            #pragma unroll
            for (int nt = 0; nt < 4; nt++) {
                u32 bh0, bh1, bl0, bl1;
                LDSM_X4(bh0, bh1, bl0, bl1,
                        vbase + lmV + (u32)((nt * 8 * 72 + 16 * kc) * 2));
                MMA16816(o[nt][0], o[nt][1], o[nt][2], o[nt][3],
                         aPh[0], aPh[1], aPh[2], aPh[3], bh0, bh1);
                MMA16816(o[nt][0], o[nt][1], o[nt][2], o[nt][3],
                         aPl[0], aPl[1], aPl[2], aPl[3], bh0, bh1);
                MMA16816(o[nt][0], o[nt][1], o[nt][2], o[nt][3],
                         aPh[0], aPh[1], aPh[2], aPh[3], bl0, bl1);
            }
        }
    }

    s0 += __shfl_xor_sync(0xffffffffu, s0, 1);
    s0 += __shfl_xor_sync(0xffffffffu, s0, 2);
    s1 += __shfl_xor_sync(0xffffffffu, s1, 1);
    s1 += __shfl_xor_sync(0xffffffffu, s1, 2);
    float i0 = 1.f / s0, i1 = 1.f / s1;

    #pragma unroll
    for (int nt = 0; nt < 4; nt++) {
        int dd = nt * 8 + fc2;
        float2 w0 = make_float2(o[nt][0] * i0, o[nt][1] * i0);
        float2 w1 = make_float2(o[nt][2] * i1, o[nt][3] * i1);
        *(float2*)&g_o[((size_t)bh * N_ + qr) * HD_ + dd]     = w0;
        *(float2*)&g_o[((size_t)bh * N_ + qr + 8) * HD_ + dd] = w1;
    }
}

// ============================================================
// K_osplit: g_o [bh][tok][d] -> channel-major bf16 splits.
// (launch index 6)
// ============================================================
__global__ void __launch_bounds__(256) osplit_kernel()
{
    __shared__ float ts[32][130];
    const int tid = threadIdx.x;
    const int chunk = blockIdx.x, bh = blockIdx.y;
    const int b = bh >> 3, h = bh & 7;
    const int tok0 = chunk * 128;
    const float* src = g_o + ((size_t)(bh * 1024 + tok0)) * 32;

    #pragma unroll
    for (int r = 0; r < 4; r++) {
        int idx = r * 256 + tid;
        int tok = idx >> 3, d4 = (idx & 7) * 4;
        float4 v = *(const float4*)&src[tok * 32 + d4];
        ts[d4][tok] = v.x; ts[d4+1][tok] = v.y; ts[d4+2][tok] = v.z; ts[d4+3][tok] = v.w;
    }
    __syncthreads();

    const int d = tid >> 3, seg = tid & 7;
    u32 hh[8], ll[8];
    #pragma unroll
    for (int i = 0; i < 8; i++) {
        float v0 = ts[d][seg * 16 + 2*i];
        float v1 = ts[d][seg * 16 + 2*i + 1];
        split2(v0, v1, hh[i], ll[i]);
    }
    size_t off = ((size_t)(b * 256 + h * 32 + d) << 10) + tok0 + seg * 16;
    *(uint4*)&g_osh[off]     = make_uint4(hh[0], hh[1], hh[2], hh[3]);
    *(uint4*)&g_osh[off + 8] = make_uint4(hh[4], hh[5], hh[6], hh[7]);
    *(uint4*)&g_osl[off]     = make_uint4(ll[0], ll[1], ll[2], ll[3]);
    *(uint4*)&g_osl[off + 8] = make_uint4(ll[4], ll[5], ll[6], ll[7]);
}

// ============================================================
// K_projgemm: output projection, 32-token tiles. (launch index 7)
// ============================================================
__global__ void __launch_bounds__(256) projgemm_kernel(
    const float* __restrict__ p1b, const float* __restrict__ p2b,
    float* __restrict__ out)
{
    __shared__ __align__(16) __nv_bfloat16 xh_s[128][40];
    __shared__ __align__(16) __nv_bfloat16 xl_s[128][40];

    const int tid  = threadIdx.x;
    const int lane = tid & 31;
    const int w    = tid >> 5;
    const int b    = blockIdx.y;
    const int tok0 = blockIdx.x * 32;
    const int r0   = w * 16 + (lane >> 2);
    const int fc2  = 2 * (lane & 3);

    const u32 xh0 = smem_u32(&xh_s[0][0]);
    const u32 xl0 = smem_u32(&xl_s[0][0]);
    const u32 lmoff = (u32)((((lane & 7) + ((lane >> 3) & 1) * 8) * 80)
                            + ((lane >> 4) & 1) * 16);

    const float* Bss[2] = {p1b, p2b};

    for (int half = 0; half < 2; half++) {
        __syncthreads();
        {
            const char* sh = (const char*)g_osh
                + (((size_t)(b * 256 + half * 128) << 10) + tok0) * 2;
            const char* sl = (const char*)g_osl
                + (((size_t)(b * 256 + half * 128) << 10) + tok0) * 2;
            #pragma unroll
            for (int r = 0; r < 2; r++) {
                int idx = r * 256 + tid;          // 0..511
                int ch = idx >> 2, seg = idx & 3;
                CP_ASYNC16(xh0 + (ch * 40 + seg * 8) * 2, sh + (size_t)ch * 2048 + seg * 16);
                CP_ASYNC16(xl0 + (ch * 40 + seg * 8) * 2, sl + (size_t)ch * 2048 + seg * 16);
            }
            CP_COMMIT(); CP_WAIT0();
        }
        __syncthreads();

        const int m = 6 + half;
        const uint4* wf = (const uint4*)g_wfrag + ((size_t)(m * 8 + w) * 24) * 32 + lane;

        float c[4][4];
        #pragma unroll
        for (int i = 0; i < 4; i++) { c[i][0] = c[i][1] = c[i][2] = c[i][3] = 0.f; }

        uint4 aa = __ldg(&wf[0]);
        #pragma unroll 4
        for (int ks = 0; ks < 24; ks++) {
            uint4 nxt = aa;
            if (ks < 23) nxt = __ldg(&wf[(ks + 1) * 32]);
            u32 bb = ((ks < 16) ? xh0 : xl0) + (u32)((ks & 7) * 16 * 80) + lmoff;
            #pragma unroll
            for (int nt = 0; nt < 2; nt++) {
                u32 f0, f1, f2, f3;
                LDSM_X4_T(f0, f1, f2, f3, bb + nt * 32);
                MMA16816(c[2*nt][0], c[2*nt][1], c[2*nt][2], c[2*nt][3],
                         aa.x, aa.y, aa.z, aa.w, f0, f1);
                MMA16816(c[2*nt+1][0], c[2*nt+1][1], c[2*nt+1][2], c[2*nt+1][3],
                         aa.x, aa.y, aa.z, aa.w, f2, f3);
            }
            aa = nxt;
        }

        float bb0 = __ldg(&Bss[half][r0]);
        float bb1 = __ldg(&Bss[half][r0 + 8]);
        float* op = out + ((size_t)(b * 256 + half * 128) << 10);
        #pragma unroll
        for (int n8 = 0; n8 < 4; n8++) {
            int tok = tok0 + n8 * 8 + fc2;
            float2 o0 = make_float2(c[n8][0] + bb0, c[n8][1] + bb0);
            float2 o1 = make_float2(c[n8][2] + bb1, c[n8][3] + bb1);
            *(float2*)&op[((size_t)r0 << 10) + tok] = o0;
            *(float2*)&op[((size_t)(r0 + 8) << 10) + tok] = o1;
        }
    }
}

// ============================================================
extern "C" void kernel_launch(void* const* d_in, const int* in_sizes, int n_in,
                              void* d_out, int out_size)
{
    const float* x    = (const float*)d_in[0];
    const float* q1w  = (const float*)d_in[1];
    const float* q1b  = (const float*)d_in[2];
    const float* q2w  = (const float*)d_in[3];
    const float* q2b  = (const float*)d_in[4];
    const float* k1w  = (const float*)d_in[5];
    const float* k1b  = (const float*)d_in[6];
    const float* k2w  = (const float*)d_in[7];
    const float* k2b  = (const float*)d_in[8];
    const float* v1w  = (const float*)d_in[9];
    const float* v1b  = (const float*)d_in[10];
    const float* v2w  = (const float*)d_in[11];
    const float* v2b  = (const float*)d_in[12];
    const float* p1w  = (const float*)d_in[13];
    const float* p1b  = (const float*)d_in[14];
    const float* p2w  = (const float*)d_in[15];
    const float* p2b  = (const float*)d_in[16];
    const float* ls   = (const float*)d_in[17];
    const float* m1w  = (const float*)d_in[18];
    const float* m1b  = (const float*)d_in[19];
    const float* m2w  = (const float*)d_in[20];
    float* out = (float*)d_out;

    // qkvgemm sits at app-launch index 3 (the ncu slot).
    wext_kernel<<<768, 256>>>(q1w, q2w, k1w, k2w, v1w, v2w, p1w, p2w);
    tab_kernel<<<(TABN_ + 255) / 256, 256>>>(m1w, m1b, m2w);
    bias_kernel<<<dim3(N_, N_ / 256), 256>>>(ls);
    qkvgemm_kernel<<<dim3(32, 16), 256>>>(x, q1b, q2b, k1b, k2b, v1b, v2b);
    normsplit_kernel<<<dim3(8, 128, 2), 128>>>();
    attn_kernel<<<dim3(N_ / 128, BH_), 256>>>(ls);
    osplit_kernel<<<dim3(8, 128), 256>>>();
    projgemm_kernel<<<dim3(32, 16), 256>>>(p1b, p2b, out);
}

// round 13
// speedup vs baseline: 1.0746x; 1.0746x over previous
#include <cuda_runtime.h>
#include <cuda_bf16.h>
#include <math.h>
#include <stdint.h>

#define B_    16
#define C_    256
#define N_    1024      // 32*32 tokens
#define NH_   8
#define HD_   32
#define HALF_ 128
#define BH_   (B_*NH_)  // 128
#define TABN_ 3969      // 63*63

typedef unsigned long long u64;
typedef unsigned int u32;

// bf16 mma m16n8k16, fp32 accum
#define MMA16816(d0,d1,d2,d3,a0,a1,a2,a3,b0,b1) \
    asm("mma.sync.aligned.m16n8k16.row.col.f32.bf16.bf16.f32 " \
        "{%0,%1,%2,%3}, {%4,%5,%6,%7}, {%8,%9}, {%0,%1,%2,%3};" \
        : "+f"(d0), "+f"(d1), "+f"(d2), "+f"(d3) \
        : "r"(a0), "r"(a1), "r"(a2), "r"(a3), "r"(b0), "r"(b1))

#define LDSM_X4(r0,r1,r2,r3,addr) \
    asm volatile("ldmatrix.sync.aligned.m8n8.x4.shared.b16 {%0,%1,%2,%3}, [%4];" \
        : "=r"(r0), "=r"(r1), "=r"(r2), "=r"(r3) : "r"(addr))

#define LDSM_X4_T(r0,r1,r2,r3,addr) \
    asm volatile("ldmatrix.sync.aligned.m8n8.x4.trans.shared.b16 {%0,%1,%2,%3}, [%4];" \
        : "=r"(r0), "=r"(r1), "=r"(r2), "=r"(r3) : "r"(addr))

#define CP_ASYNC16(dst,src) \
    asm volatile("cp.async.cg.shared.global [%0], [%1], 16;" :: "r"(dst), "l"(src))
#define CP_COMMIT() asm volatile("cp.async.commit_group;")
#define CP_WAIT0()  asm volatile("cp.async.wait_group 0;")

__device__ __forceinline__ u32 smem_u32(const void* p) {
    u32 a;
    asm("{ .reg .u64 t; cvta.to.shared.u64 t, %1; cvt.u32.u64 %0, t; }"
        : "=r"(a) : "l"(p));
    return a;
}

// ---- scratch (device globals; no runtime allocation allowed) ----
__device__ float g_q[B_*C_*N_];             // 16 MB, [b][c][tok]
__device__ float g_k[B_*C_*N_];             // 16 MB
__device__ float g_v[B_*C_*N_];             // 16 MB
__device__ u32 g_wfrag[8*8*24*32*4];        // pre-swizzled A-fragments (qkv+proj)
__device__ __nv_bfloat16 g_qs[BH_*N_*96];   // [qh|ql|qh]  25 MB
__device__ __nv_bfloat16 g_ks[BH_*N_*96];   // [kh|kh|kl]  25 MB
__device__ __nv_bfloat16 g_vt[BH_*64*N_];   // [bh][vh|vl][key] 16 MB
__device__ float g_o[BH_*N_*HD_];           // 16 MB
__device__ __nv_bfloat16 g_osh[B_*C_*N_];   // attn out, high split, [b][c][tok]
__device__ __nv_bfloat16 g_osl[B_*C_*N_];   // low split
__device__ float g_tab[TABN_*NH_];
__device__ float g_biasB[NH_*N_*N_];        // 32 MB, [h][query][key], pre-scaled

__device__ __forceinline__ u32 pkh(__nv_bfloat16 a, __nv_bfloat16 b) {
    __nv_bfloat162 t; t.x = a; t.y = b;
    return *(u32*)&t;
}
__device__ __forceinline__ u32 pkf(float a, float b) {
    __nv_bfloat162 t = __floats2bfloat162_rn(a, b);
    return *(u32*)&t;
}
// split (v0,v1) into packed bf16x2 high + low words (low lane = v0)
__device__ __forceinline__ void split2(float v0, float v1, u32& hw, u32& lw) {
    asm("cvt.rn.bf16x2.f32 %0, %1, %2;" : "=r"(hw) : "f"(v1), "f"(v0));
    float h0 = __uint_as_float(hw << 16);
    float h1 = __uint_as_float(hw & 0xffff0000u);
    float l0 = v0 - h0, l1 = v1 - h1;
    asm("cvt.rn.bf16x2.f32 %0, %1, %2;" : "=r"(lw) : "f"(l1), "f"(l0));
}

// ============================================================
// K_wext: pre-swizzled split-weight A-fragments, K-ext [wh|wl|wh].
// (launch index 0)
// ============================================================
__global__ void __launch_bounds__(256) wext_kernel(
    const float* __restrict__ q1w, const float* __restrict__ q2w,
    const float* __restrict__ k1w, const float* __restrict__ k2w,
    const float* __restrict__ v1w, const float* __restrict__ v2w,
    const float* __restrict__ p1w, const float* __restrict__ p2w)
{
    const float* Ws[8] = {q1w, q2w, k1w, k2w, v1w, v2w, p1w, p2w};
    int id = blockIdx.x * 256 + threadIdx.x;   // 0..196607
    int j    = id & 3;
    int lane = (id >> 2) & 31;
    int ks   = (id >> 7) % 24;
    int rbm  = id / (128 * 24);
    int rb = rbm & 7, m = rbm >> 3;
    int row = rb * 16 + (lane >> 2) + (j & 1) * 8;
    int col = ks * 16 + 2 * (lane & 3) + ((j >> 1) & 1) * 8;
    int region = col >> 7, ic = col & 127;
    const float* W = Ws[m];
    float v0 = W[row * 128 + ic], v1 = W[row * 128 + ic + 1];
    u32 r;
    if (region == 1) {
        __nv_bfloat16 h0 = __float2bfloat16(v0), h1 = __float2bfloat16(v1);
        r = pkf(v0 - __bfloat162float(h0), v1 - __bfloat162float(h1));
    } else {
        r = pkh(__float2bfloat16(v0), __float2bfloat16(v1));
    }
    g_wfrag[id] = r;
}

// ============================================================
// K2: CPB table MLP (launch index 1)
// ============================================================
__global__ void __launch_bounds__(256) tab_kernel(
    const float* __restrict__ w1, const float* __restrict__ b1,
    const float* __restrict__ w2)
{
    __shared__ float w1s[256];
    __shared__ float b1s[128];
    __shared__ float w2s[1024];
    int tid = threadIdx.x;
    if (tid < 256) w1s[tid] = w1[tid];
    if (tid < 128) b1s[tid] = b1[tid];
    for (int i = tid; i < 1024; i += 256) w2s[i] = w2[i];
    __syncthreads();

    int p = blockIdx.x * 256 + tid;
    if (p >= TABN_) return;
    int a = p / 63, b = p % 63;
    float t0 = ((float)(a - 31) / 31.0f) * 3.2f;
    float t1 = ((float)(b - 31) / 31.0f) * 3.2f;
    t0 = copysignf(1.f - __expf(-fabsf(t0)), t0);
    t1 = copysignf(1.f - __expf(-fabsf(t1)), t1);

    float acc[NH_];
    #pragma unroll
    for (int h = 0; h < NH_; h++) acc[h] = 0.f;
    for (int k = 0; k < 128; k++) {
        float hv = fmaxf(w1s[2 * k] * t0 + w1s[2 * k + 1] * t1 + b1s[k], 0.f);
        #pragma unroll
        for (int h = 0; h < NH_; h++) acc[h] += w2s[h * 128 + k] * hv;
    }
    #pragma unroll
    for (int h = 0; h < NH_; h++) g_tab[p * NH_ + h] = acc[h];
}

// ============================================================
// K3: expand bias, pre-scaled (bias - M_h)*log2e. (launch index 2)
// ============================================================
__global__ void __launch_bounds__(256) bias_kernel(const float* __restrict__ ls)
{
    __shared__ float mh[NH_];
    if (threadIdx.x < NH_)
        mh[threadIdx.x] = __expf(fminf(ls[threadIdx.x], 4.6051702f)) + 16.f;
    __syncthreads();

    int n = blockIdx.x;                       // query
    int m = blockIdx.y * 256 + threadIdx.x;   // key
    int i = n >> 5, j = n & 31;
    int p = m >> 5, q = m & 31;
    int idx = (i - p + 31) * 63 + (j - q + 31);
    const float* t = g_tab + idx * NH_;
    #pragma unroll
    for (int h = 0; h < NH_; h++) {
        float v = 16.f / (1.f + __expf(-t[h]));
        g_biasB[((size_t)h * N_ + n) * N_ + m] = (v - mh[h]) * 1.44269504f;
    }
}

// ============================================================
// K_qkvgemm: R10 configuration (best measured: 46 us).
// 64-token tiles, grid (16,16), no A-prefetch, fp32 q/k/v out.
// (launch index 3 — ncu slot)
// ============================================================
__global__ void __launch_bounds__(256) qkvgemm_kernel(
    const float* __restrict__ x,
    const float* __restrict__ q1b, const float* __restrict__ q2b,
    const float* __restrict__ k1b, const float* __restrict__ k2b,
    const float* __restrict__ v1b, const float* __restrict__ v2b)
{
    __shared__ __align__(16) __nv_bfloat16 xh_s[128][72];
    __shared__ __align__(16) __nv_bfloat16 xl_s[128][72];

    const int tid  = threadIdx.x;
    const int lane = tid & 31;
    const int w    = tid >> 5;
    const int b    = blockIdx.y;
    const int tok0 = blockIdx.x * 64;
    const int r0   = w * 16 + (lane >> 2);
    const int fc2  = 2 * (lane & 3);

    const u32 xh0 = smem_u32(&xh_s[0][0]);
    const u32 xl0 = smem_u32(&xl_s[0][0]);
    const u32 lmoff = (u32)((((lane & 7) + ((lane >> 3) & 1) * 8) * 144)
                            + ((lane >> 4) & 1) * 16);

    const float* Bss[6] = {q1b, q2b, k1b, k2b, v1b, v2b};
    float* Outs[3] = {g_q, g_k, g_v};

    for (int half = 0; half < 2; half++) {
        __syncthreads();
        #pragma unroll
        for (int r = 0; r < 8; r++) {
            int idx = r * 256 + tid;
            int ch = idx >> 4, t4 = (idx & 15) * 4;
            float4 xv = *(const float4*)&x[((size_t)(b * 256 + half * 128 + ch) << 10) + tok0 + t4];
            u32 hw0, lw0, hw1, lw1;
            split2(xv.x, xv.y, hw0, lw0);
            split2(xv.z, xv.w, hw1, lw1);
            *(uint2*)&xh_s[ch][t4] = make_uint2(hw0, hw1);
            *(uint2*)&xl_s[ch][t4] = make_uint2(lw0, lw1);
        }
        __syncthreads();

        for (int g = 0; g < 3; g++) {
            const int m = g * 2 + half;
            const uint4* wf = (const uint4*)g_wfrag + ((size_t)(m * 8 + w) * 24) * 32 + lane;

            float c[8][4];
            #pragma unroll
            for (int i = 0; i < 8; i++) { c[i][0] = c[i][1] = c[i][2] = c[i][3] = 0.f; }

            #pragma unroll 4
            for (int ks = 0; ks < 24; ks++) {
                uint4 aa = __ldg(&wf[ks * 32]);   // coalesced LDG.128
                u32 bb = ((ks < 16) ? xh0 : xl0) + (u32)((ks & 7) * 16 * 144) + lmoff;
                #pragma unroll
                for (int nt = 0; nt < 4; nt++) {
                    u32 f0, f1, f2, f3;
                    LDSM_X4_T(f0, f1, f2, f3, bb + nt * 32);
                    MMA16816(c[2*nt][0], c[2*nt][1], c[2*nt][2], c[2*nt][3],
                             aa.x, aa.y, aa.z, aa.w, f0, f1);
                    MMA16816(c[2*nt+1][0], c[2*nt+1][1], c[2*nt+1][2], c[2*nt+1][3],
                             aa.x, aa.y, aa.z, aa.w, f2, f3);
                }
            }

            float bb0 = __ldg(&Bss[m][r0]);
            float bb1 = __ldg(&Bss[m][r0 + 8]);
            const float* xr = x + ((size_t)(b * 256 + half * 128) << 10);
            float* op = Outs[g] + ((size_t)(b * 256 + half * 128) << 10);
            #pragma unroll
            for (int n8 = 0; n8 < 8; n8++) {
                int tok = tok0 + n8 * 8 + fc2;
                float2 rx0 = *(const float2*)&xr[((size_t)r0 << 10) + tok];
                float2 rx1 = *(const float2*)&xr[((size_t)(r0 + 8) << 10) + tok];
                float2 o0 = make_float2(c[n8][0] + rx0.x + bb0, c[n8][1] + rx0.y + bb0);
                float2 o1 = make_float2(c[n8][2] + rx1.x + bb1, c[n8][3] + rx1.y + bb1);
                *(float2*)&op[((size_t)r0 << 10) + tok] = o0;
                *(float2*)&op[((size_t)(r0 + 8) << 10) + tok] = o1;
            }
        }
    }
}

// ============================================================
// K_normsplit (launch index 4)
// ============================================================
__global__ void __launch_bounds__(128) normsplit_kernel()
{
    __shared__ float xs[32][129];
    __shared__ u32 os[128][49];

    const int tid = threadIdx.x;
    const int chunk = blockIdx.x, bh = blockIdx.y, qk = blockIdx.z;
    const int b = bh >> 3, h = bh & 7;
    const int tok0 = chunk * 128;
    const float* src = (qk ? g_k : g_q) + ((size_t)(b * 256 + h * 32) << 10) + tok0;

    #pragma unroll
    for (int r = 0; r < 8; r++) {
        int idx = r * 128 + tid;
        int ch = idx >> 5, t4 = (idx & 31) * 4;
        float4 v = *(const float4*)&src[((size_t)ch << 10) + t4];
        xs[ch][t4] = v.x; xs[ch][t4+1] = v.y; xs[ch][t4+2] = v.z; xs[ch][t4+3] = v.w;
    }
    __syncthreads();

    float vals[32]; float s = 0.f;
    #pragma unroll
    for (int ch = 0; ch < 32; ch++) { vals[ch] = xs[ch][tid]; s += vals[ch] * vals[ch]; }
    float inv = 1.f / fmaxf(sqrtf(s), 1e-12f);

    #pragma unroll
    for (int j = 0; j < 16; j++) {
        float v0 = vals[2*j] * inv, v1 = vals[2*j+1] * inv;
        u32 hh, ll;
        split2(v0, v1, hh, ll);
        if (qk == 0) { os[tid][j] = hh; os[tid][16+j] = ll; os[tid][32+j] = hh; }
        else         { os[tid][j] = hh; os[tid][16+j] = hh; os[tid][32+j] = ll; }
    }
    __syncthreads();

    __nv_bfloat16* dst = (qk ? g_ks : g_qs) + ((size_t)bh * N_ + tok0) * 96;
    #pragma unroll
    for (int r = 0; r < 12; r++) {
        int idx = r * 128 + tid;
        int row = idx / 12, seg = idx % 12;
        uint4 v = make_uint4(os[row][seg*4], os[row][seg*4+1],
                             os[row][seg*4+2], os[row][seg*4+3]);
        *(uint4*)(dst + (size_t)row * 96 + seg * 8) = v;
    }
}

// ============================================================
// K_vsplit: v [b][c][tok] -> g_vt [bh][vh|vl][tok]. (launch index 5)
// ============================================================
__global__ void __launch_bounds__(256) vsplit_kernel()
{
    const int row = blockIdx.x;            // b*256 + c
    const int b = row >> 8, c = row & 255;
    const int h = c >> 5, d = c & 31;
    const float* src = g_v + ((size_t)row << 10);
    __nv_bfloat16* dh = g_vt + (((size_t)(b * 8 + h)) * 64 + d) * 1024;
    __nv_bfloat16* dl = dh + 32 * 1024;
    int t4 = threadIdx.x * 4;
    float4 v = *(const float4*)&src[t4];
    u32 hw0, lw0, hw1, lw1;
    split2(v.x, v.y, hw0, lw0);
    split2(v.z, v.w, hw1, lw1);
    *(uint2*)&dh[t4] = make_uint2(hw0, hw1);
    *(uint2*)&dl[t4] = make_uint2(lw0, lw1);
}

// ============================================================
// K4: attention — chunked softmax (R11 best), (256,2), deduped aQ.
// (launch index 6)
// ============================================================
__global__ void __launch_bounds__(256, 2) attn_kernel(const float* __restrict__ logit_scale)
{
    __shared__ __align__(16) __nv_bfloat16 ks_s[2][64][104];
    __shared__ __align__(16) __nv_bfloat16 vt_s[2][64][72];

    const int tid  = threadIdx.x;
    const int lane = tid & 31;
    const int w    = tid >> 5;
    const int bh   = blockIdx.y;
    const int h    = bh & 7;
    const int q0   = blockIdx.x * 128;
    const int qr   = q0 + w * 16 + (lane >> 2);
    const int fc2  = 2 * (lane & 3);

    // K-ext layout [qh|ql|qh]: ksteps 4,5 duplicate 0,1 -> load 4 only
    u32 aQ[4][4];
    {
        const __nv_bfloat16* qb = g_qs + ((size_t)bh * N_ + qr) * 96;
        #pragma unroll
        for (int ks = 0; ks < 4; ks++) {
            int f = fc2 + 16 * ks;
            aQ[ks][0] = *(const u32*)(qb + f);
            aQ[ks][1] = *(const u32*)(qb + 8 * 96 + f);
            aQ[ks][2] = *(const u32*)(qb + f + 8);
            aQ[ks][3] = *(const u32*)(qb + 8 * 96 + f + 8);
        }
    }

    const float scale = __expf(fminf(logit_scale[h], 4.6051702f));
    const float sl2e  = scale * 1.44269504f;

    float o[4][4];
    #pragma unroll
    for (int i = 0; i < 4; i++)
        #pragma unroll
        for (int j = 0; j < 4; j++) o[i][j] = 0.f;
    float s0 = 0.f, s1 = 0.f;

    const float* bias0 = g_biasB + ((size_t)h * N_ + qr) * N_;
    const float* bias1 = bias0 + (size_t)8 * N_;

    const u32 ks0 = smem_u32(&ks_s[0][0][0]);
    const u32 vt0 = smem_u32(&vt_s[0][0][0]);
    const u32 KSB = 64 * 104 * 2;
    const u32 VTB = 64 * 72 * 2;

    const u32 lmK = (u32)(((((lane >> 4) & 1) * 8 + (lane & 7)) * 104
                           + ((lane >> 3) & 1) * 8) * 2);
    const u32 lmV = (u32)(((((lane >> 4) & 1) * 32 + (lane & 7)) * 72
                           + ((lane >> 3) & 1) * 8) * 2);

    const char* kgbase = (const char*)(g_ks + (size_t)bh * N_ * 96);
    const char* vgbase = (const char*)(g_vt + (size_t)bh * 64 * N_);

    auto stage = [&](int kt, int bf) {
        const char* src = kgbase + (size_t)kt * 64 * 192;
        u32 dst = ks0 + bf * KSB;
        #pragma unroll
        for (int i = 0; i < 3; i++) {
            int idx = i * 256 + tid;
            int key = idx / 12, seg = idx % 12;
            CP_ASYNC16(dst + (key * 104 + seg * 8) * 2, src + key * 192 + seg * 16);
        }
        const char* vs = vgbase + (size_t)kt * 64 * 2;
        u32 vdst = vt0 + bf * VTB;
        #pragma unroll
        for (int i = 0; i < 2; i++) {
            int idx = i * 256 + tid;
            int f = idx / 8, seg = idx % 8;
            CP_ASYNC16(vdst + (f * 72 + seg * 8) * 2, vs + (size_t)f * N_ * 2 + seg * 16);
        }
        CP_COMMIT();
    };

    stage(0, 0);

    for (int kt = 0; kt < 16; kt++) {
        const int buf = kt & 1;
        CP_WAIT0();
        __syncthreads();
        if (kt < 15) stage(kt + 1, buf ^ 1);

        const u32 kbase = ks0 + buf * KSB;
        const u32 vbase = vt0 + buf * VTB;

        #pragma unroll
        for (int kc = 0; kc < 4; kc++) {
            // ---- QK^T for 16 keys ----
            float c[2][4];
            c[0][0] = c[0][1] = c[0][2] = c[0][3] = 0.f;
            c[1][0] = c[1][1] = c[1][2] = c[1][3] = 0.f;
            #pragma unroll
            for (int ks = 0; ks < 6; ks++) {
                const int qi = (ks < 4) ? ks : ks - 4;
                u32 b00, b01, b10, b11;
                LDSM_X4(b00, b01, b10, b11,
                        kbase + lmK + (u32)((kc * 16 * 104 + 16 * ks) * 2));
                MMA16816(c[0][0], c[0][1], c[0][2], c[0][3],
                         aQ[qi][0], aQ[qi][1], aQ[qi][2], aQ[qi][3], b00, b01);
                MMA16816(c[1][0], c[1][1], c[1][2], c[1][3],
                         aQ[qi][0], aQ[qi][1], aQ[qi][2], aQ[qi][3], b10, b11);
            }

            // ---- softmax slice (bias pre-scaled by log2e, M folded) ----
            int kg = kt * 64 + kc * 16 + fc2;
            float2 bb0 = *(const float2*)(bias0 + kg);
            float2 bb1 = *(const float2*)(bias1 + kg);
            float2 bb2 = *(const float2*)(bias0 + kg + 8);
            float2 bb3 = *(const float2*)(bias1 + kg + 8);
            float pv0 = exp2f(fmaf(c[0][0], sl2e, bb0.x));
            float pv1 = exp2f(fmaf(c[0][1], sl2e, bb0.y));
            float pv2 = exp2f(fmaf(c[0][2], sl2e, bb1.x));
            float pv3 = exp2f(fmaf(c[0][3], sl2e, bb1.y));
            float pw0 = exp2f(fmaf(c[1][0], sl2e, bb2.x));
            float pw1 = exp2f(fmaf(c[1][1], sl2e, bb2.y));
            float pw2 = exp2f(fmaf(c[1][2], sl2e, bb3.x));
            float pw3 = exp2f(fmaf(c[1][3], sl2e, bb3.y));
            s0 += (pv0 + pv1) + (pw0 + pw1);
            s1 += (pv2 + pv3) + (pw2 + pw3);

            u32 aPh[4], aPl[4];
            split2(pv0, pv1, aPh[0], aPl[0]);
            split2(pv2, pv3, aPh[1], aPl[1]);
            split2(pw0, pw1, aPh[2], aPl[2]);
            split2(pw2, pw3, aPh[3], aPl[3]);

            // ---- P·V for these 16 keys ----
            #pragma unroll
            for (int nt = 0; nt < 4; nt++) {
                u32 bh0, bh1, bl0, bl1;
                LDSM_X4(bh0, bh1, bl0, bl1,
                        vbase + lmV + (u32)((nt * 8 * 72 + 16 * kc) * 2));
                MMA16816(o[nt][0], o[nt][1], o[nt][2], o[nt][3],
                         aPh[0], aPh[1], aPh[2], aPh[3], bh0, bh1);
                MMA16816(o[nt][0], o[nt][1], o[nt][2], o[nt][3],
                         aPl[0], aPl[1], aPl[2], aPl[3], bh0, bh1);
                MMA16816(o[nt][0], o[nt][1], o[nt][2], o[nt][3],
                         aPh[0], aPh[1], aPh[2], aPh[3], bl0, bl1);
            }
        }
    }

    s0 += __shfl_xor_sync(0xffffffffu, s0, 1);
    s0 += __shfl_xor_sync(0xffffffffu, s0, 2);
    s1 += __shfl_xor_sync(0xffffffffu, s1, 1);
    s1 += __shfl_xor_sync(0xffffffffu, s1, 2);
    float i0 = 1.f / s0, i1 = 1.f / s1;

    #pragma unroll
    for (int nt = 0; nt < 4; nt++) {
        int dd = nt * 8 + fc2;
        float2 w0 = make_float2(o[nt][0] * i0, o[nt][1] * i0);
        float2 w1 = make_float2(o[nt][2] * i1, o[nt][3] * i1);
        *(float2*)&g_o[((size_t)bh * N_ + qr) * HD_ + dd]     = w0;
        *(float2*)&g_o[((size_t)bh * N_ + qr + 8) * HD_ + dd] = w1;
    }
}

// ============================================================
// K_osplit: g_o [bh][tok][d] -> channel-major bf16 splits.
// (launch index 7)
// ============================================================
__global__ void __launch_bounds__(256) osplit_kernel()
{
    __shared__ float ts[32][130];
    const int tid = threadIdx.x;
    const int chunk = blockIdx.x, bh = blockIdx.y;
    const int b = bh >> 3, h = bh & 7;
    const int tok0 = chunk * 128;
    const float* src = g_o + ((size_t)(bh * 1024 + tok0)) * 32;

    #pragma unroll
    for (int r = 0; r < 4; r++) {
        int idx = r * 256 + tid;
        int tok = idx >> 3, d4 = (idx & 7) * 4;
        float4 v = *(const float4*)&src[tok * 32 + d4];
        ts[d4][tok] = v.x; ts[d4+1][tok] = v.y; ts[d4+2][tok] = v.z; ts[d4+3][tok] = v.w;
    }
    __syncthreads();

    const int d = tid >> 3, seg = tid & 7;
    u32 hh[8], ll[8];
    #pragma unroll
    for (int i = 0; i < 8; i++) {
        float v0 = ts[d][seg * 16 + 2*i];
        float v1 = ts[d][seg * 16 + 2*i + 1];
        split2(v0, v1, hh[i], ll[i]);
    }
    size_t off = ((size_t)(b * 256 + h * 32 + d) << 10) + tok0 + seg * 16;
    *(uint4*)&g_osh[off]     = make_uint4(hh[0], hh[1], hh[2], hh[3]);
    *(uint4*)&g_osh[off + 8] = make_uint4(hh[4], hh[5], hh[6], hh[7]);
    *(uint4*)&g_osl[off]     = make_uint4(ll[0], ll[1], ll[2], ll[3]);
    *(uint4*)&g_osl[off + 8] = make_uint4(ll[4], ll[5], ll[6], ll[7]);
}

// ============================================================
// K_projgemm: output projection, 64-token tiles (R10 config).
// (launch index 8)
// ============================================================
__global__ void __launch_bounds__(256) projgemm_kernel(
    const float* __restrict__ p1b, const float* __restrict__ p2b,
    float* __restrict__ out)
{
    __shared__ __align__(16) __nv_bfloat16 xh_s[128][72];
    __shared__ __align__(16) __nv_bfloat16 xl_s[128][72];

    const int tid  = threadIdx.x;
    const int lane = tid & 31;
    const int w    = tid >> 5;
    const int b    = blockIdx.y;
    const int tok0 = blockIdx.x * 64;
    const int r0   = w * 16 + (lane >> 2);
    const int fc2  = 2 * (lane & 3);

    const u32 xh0 = smem_u32(&xh_s[0][0]);
    const u32 xl0 = smem_u32(&xl_s[0][0]);
    const u32 lmoff = (u32)((((lane & 7) + ((lane >> 3) & 1) * 8) * 144)
                            + ((lane >> 4) & 1) * 16);

    const float* Bss[2] = {p1b, p2b};

    for (int half = 0; half < 2; half++) {
        __syncthreads();
        {
            const char* sh = (const char*)g_osh
                + (((size_t)(b * 256 + half * 128) << 10) + tok0) * 2;
            const char* sl = (const char*)g_osl
                + (((size_t)(b * 256 + half * 128) << 10) + tok0) * 2;
            #pragma unroll
            for (int r = 0; r < 4; r++) {
                int idx = r * 256 + tid;
                int ch = idx >> 3, seg = idx & 7;
                CP_ASYNC16(xh0 + (ch * 72 + seg * 8) * 2, sh + ((size_t)ch << 11) + seg * 16);
                CP_ASYNC16(xl0 + (ch * 72 + seg * 8) * 2, sl + ((size_t)ch << 11) + seg * 16);
            }
            CP_COMMIT(); CP_WAIT0();
        }
        __syncthreads();

        const int m = 6 + half;
        const uint4* wf = (const uint4*)g_wfrag + ((size_t)(m * 8 + w) * 24) * 32 + lane;

        float c[8][4];
        #pragma unroll
        for (int i = 0; i < 8; i++) { c[i][0] = c[i][1] = c[i][2] = c[i][3] = 0.f; }

        #pragma unroll 4
        for (int ks = 0; ks < 24; ks++) {
            uint4 aa = __ldg(&wf[ks * 32]);
            u32 bb = ((ks < 16) ? xh0 : xl0) + (u32)((ks & 7) * 16 * 144) + lmoff;
            #pragma unroll
            for (int nt = 0; nt < 4; nt++) {
                u32 f0, f1, f2, f3;
                LDSM_X4_T(f0, f1, f2, f3, bb + nt * 32);
                MMA16816(c[2*nt][0], c[2*nt][1], c[2*nt][2], c[2*nt][3],
                         aa.x, aa.y, aa.z, aa.w, f0, f1);
                MMA16816(c[2*nt+1][0], c[2*nt+1][1], c[2*nt+1][2], c[2*nt+1][3],
                         aa.x, aa.y, aa.z, aa.w, f2, f3);
            }
        }

        float bb0 = __ldg(&Bss[half][r0]);
        float bb1 = __ldg(&Bss[half][r0 + 8]);
        float* op = out + ((size_t)(b * 256 + half * 128) << 10);
        #pragma unroll
        for (int n8 = 0; n8 < 8; n8++) {
            int tok = tok0 + n8 * 8 + fc2;
            float2 o0 = make_float2(c[n8][0] + bb0, c[n8][1] + bb0);
            float2 o1 = make_float2(c[n8][2] + bb1, c[n8][3] + bb1);
            *(float2*)&op[((size_t)r0 << 10) + tok] = o0;
            *(float2*)&op[((size_t)(r0 + 8) << 10) + tok] = o1;
        }
    }
}

// ============================================================
extern "C" void kernel_launch(void* const* d_in, const int* in_sizes, int n_in,
                              void* d_out, int out_size)
{
    const float* x    = (const float*)d_in[0];
    const float* q1w  = (const float*)d_in[1];
    const float* q1b  = (const float*)d_in[2];
    const float* q2w  = (const float*)d_in[3];
    const float* q2b  = (const float*)d_in[4];
    const float* k1w  = (const float*)d_in[5];
    const float* k1b  = (const float*)d_in[6];
    const float* k2w  = (const float*)d_in[7];
    const float* k2b  = (const float*)d_in[8];
    const float* v1w  = (const float*)d_in[9];
    const float* v1b  = (const float*)d_in[10];
    const float* v2w  = (const float*)d_in[11];
    const float* v2b  = (const float*)d_in[12];
    const float* p1w  = (const float*)d_in[13];
    const float* p1b  = (const float*)d_in[14];
    const float* p2w  = (const float*)d_in[15];
    const float* p2b  = (const float*)d_in[16];
    const float* ls   = (const float*)d_in[17];
    const float* m1w  = (const float*)d_in[18];
    const float* m1b  = (const float*)d_in[19];
    const float* m2w  = (const float*)d_in[20];
    float* out = (float*)d_out;

    // qkvgemm sits at app-launch index 3 (the ncu slot).
    wext_kernel<<<768, 256>>>(q1w, q2w, k1w, k2w, v1w, v2w, p1w, p2w);
    tab_kernel<<<(TABN_ + 255) / 256, 256>>>(m1w, m1b, m2w);
    bias_kernel<<<dim3(N_, N_ / 256), 256>>>(ls);
    qkvgemm_kernel<<<dim3(16, 16), 256>>>(x, q1b, q2b, k1b, k2b, v1b, v2b);
    normsplit_kernel<<<dim3(8, 128, 2), 128>>>();
    vsplit_kernel<<<4096, 256>>>();
    attn_kernel<<<dim3(N_ / 128, BH_), 256>>>(ls);
    osplit_kernel<<<dim3(8, 128), 256>>>();
    projgemm_kernel<<<dim3(16, 16), 256>>>(p1b, p2b, out);
}

// round 14
// speedup vs baseline: 1.1124x; 1.0351x over previous
#include <cuda_runtime.h>
#include <cuda_bf16.h>
#include <cuda_fp16.h>
#include <math.h>
#include <stdint.h>

#define B_    16
#define C_    256
#define N_    1024      // 32*32 tokens
#define NH_   8
#define HD_   32
#define HALF_ 128
#define BH_   (B_*NH_)  // 128
#define TABN_ 3969      // 63*63

typedef unsigned long long u64;
typedef unsigned int u32;

// bf16 mma m16n8k16, fp32 accum
#define MMA16816(d0,d1,d2,d3,a0,a1,a2,a3,b0,b1) \
    asm("mma.sync.aligned.m16n8k16.row.col.f32.bf16.bf16.f32 " \
        "{%0,%1,%2,%3}, {%4,%5,%6,%7}, {%8,%9}, {%0,%1,%2,%3};" \
        : "+f"(d0), "+f"(d1), "+f"(d2), "+f"(d3) \
        : "r"(a0), "r"(a1), "r"(a2), "r"(a3), "r"(b0), "r"(b1))

#define LDSM_X4(r0,r1,r2,r3,addr) \
    asm volatile("ldmatrix.sync.aligned.m8n8.x4.shared.b16 {%0,%1,%2,%3}, [%4];" \
        : "=r"(r0), "=r"(r1), "=r"(r2), "=r"(r3) : "r"(addr))

#define LDSM_X4_T(r0,r1,r2,r3,addr) \
    asm volatile("ldmatrix.sync.aligned.m8n8.x4.trans.shared.b16 {%0,%1,%2,%3}, [%4];" \
        : "=r"(r0), "=r"(r1), "=r"(r2), "=r"(r3) : "r"(addr))

#define CP_ASYNC16(dst,src) \
    asm volatile("cp.async.cg.shared.global [%0], [%1], 16;" :: "r"(dst), "l"(src))
#define CP_COMMIT() asm volatile("cp.async.commit_group;")
#define CP_WAIT0()  asm volatile("cp.async.wait_group 0;")

// guaranteed single-MUFU exp2
__device__ __forceinline__ float ex2(float x) {
    float r;
    asm("ex2.approx.f32 %0, %1;" : "=f"(r) : "f"(x));
    return r;
}

__device__ __forceinline__ u32 smem_u32(const void* p) {
    u32 a;
    asm("{ .reg .u64 t; cvta.to.shared.u64 t, %1; cvt.u32.u64 %0, t; }"
        : "=r"(a) : "l"(p));
    return a;
}

// ---- scratch (device globals; no runtime allocation allowed) ----
__device__ float g_q[B_*C_*N_];             // 16 MB, [b][c][tok]
__device__ float g_k[B_*C_*N_];             // 16 MB
__device__ float g_v[B_*C_*N_];             // 16 MB
__device__ u32 g_wfrag[8*8*24*32*4];        // pre-swizzled A-fragments (qkv+proj)
__device__ __nv_bfloat16 g_qs[BH_*N_*96];   // [qh|ql|qh]  25 MB
__device__ __nv_bfloat16 g_ks[BH_*N_*96];   // [kh|kh|kl]  25 MB
__device__ __nv_bfloat16 g_vt[BH_*64*N_];   // [bh][vh|vl][key] 16 MB
__device__ float g_o[BH_*N_*HD_];           // 16 MB
__device__ __nv_bfloat16 g_osh[B_*C_*N_];   // attn out, high split, [b][c][tok]
__device__ __nv_bfloat16 g_osl[B_*C_*N_];   // low split
__device__ float g_tab[TABN_*NH_];
__device__ __half g_biasH[NH_*N_*N_];       // 16 MB, [h][query][key], (b-M)*log2e

__device__ __forceinline__ u32 pkh(__nv_bfloat16 a, __nv_bfloat16 b) {
    __nv_bfloat162 t; t.x = a; t.y = b;
    return *(u32*)&t;
}
__device__ __forceinline__ u32 pkf(float a, float b) {
    __nv_bfloat162 t = __floats2bfloat162_rn(a, b);
    return *(u32*)&t;
}
// split (v0,v1) into packed bf16x2 high + low words (low lane = v0)
__device__ __forceinline__ void split2(float v0, float v1, u32& hw, u32& lw) {
    asm("cvt.rn.bf16x2.f32 %0, %1, %2;" : "=r"(hw) : "f"(v1), "f"(v0));
    float h0 = __uint_as_float(hw << 16);
    float h1 = __uint_as_float(hw & 0xffff0000u);
    float l0 = v0 - h0, l1 = v1 - h1;
    asm("cvt.rn.bf16x2.f32 %0, %1, %2;" : "=r"(lw) : "f"(l1), "f"(l0));
}

// ============================================================
// K_wext: pre-swizzled split-weight A-fragments, K-ext [wh|wl|wh].
// (launch index 0)
// ============================================================
__global__ void __launch_bounds__(256) wext_kernel(
    const float* __restrict__ q1w, const float* __restrict__ q2w,
    const float* __restrict__ k1w, const float* __restrict__ k2w,
    const float* __restrict__ v1w, const float* __restrict__ v2w,
    const float* __restrict__ p1w, const float* __restrict__ p2w)
{
    const float* Ws[8] = {q1w, q2w, k1w, k2w, v1w, v2w, p1w, p2w};
    int id = blockIdx.x * 256 + threadIdx.x;   // 0..196607
    int j    = id & 3;
    int lane = (id >> 2) & 31;
    int ks   = (id >> 7) % 24;
    int rbm  = id / (128 * 24);
    int rb = rbm & 7, m = rbm >> 3;
    int row = rb * 16 + (lane >> 2) + (j & 1) * 8;
    int col = ks * 16 + 2 * (lane & 3) + ((j >> 1) & 1) * 8;
    int region = col >> 7, ic = col & 127;
    const float* W = Ws[m];
    float v0 = W[row * 128 + ic], v1 = W[row * 128 + ic + 1];
    u32 r;
    if (region == 1) {
        __nv_bfloat16 h0 = __float2bfloat16(v0), h1 = __float2bfloat16(v1);
        r = pkf(v0 - __bfloat162float(h0), v1 - __bfloat162float(h1));
    } else {
        r = pkh(__float2bfloat16(v0), __float2bfloat16(v1));
    }
    g_wfrag[id] = r;
}

// ============================================================
// K2: CPB table MLP (launch index 1)
// ============================================================
__global__ void __launch_bounds__(256) tab_kernel(
    const float* __restrict__ w1, const float* __restrict__ b1,
    const float* __restrict__ w2)
{
    __shared__ float w1s[256];
    __shared__ float b1s[128];
    __shared__ float w2s[1024];
    int tid = threadIdx.x;
    if (tid < 256) w1s[tid] = w1[tid];
    if (tid < 128) b1s[tid] = b1[tid];
    for (int i = tid; i < 1024; i += 256) w2s[i] = w2[i];
    __syncthreads();

    int p = blockIdx.x * 256 + tid;
    if (p >= TABN_) return;
    int a = p / 63, b = p % 63;
    float t0 = ((float)(a - 31) / 31.0f) * 3.2f;
    float t1 = ((float)(b - 31) / 31.0f) * 3.2f;
    t0 = copysignf(1.f - __expf(-fabsf(t0)), t0);
    t1 = copysignf(1.f - __expf(-fabsf(t1)), t1);

    float acc[NH_];
    #pragma unroll
    for (int h = 0; h < NH_; h++) acc[h] = 0.f;
    for (int k = 0; k < 128; k++) {
        float hv = fmaxf(w1s[2 * k] * t0 + w1s[2 * k + 1] * t1 + b1s[k], 0.f);
        #pragma unroll
        for (int h = 0; h < NH_; h++) acc[h] += w2s[h * 128 + k] * hv;
    }
    #pragma unroll
    for (int h = 0; h < NH_; h++) g_tab[p * NH_ + h] = acc[h];
}

// ============================================================
// K3: expand bias to fp16, pre-scaled (bias - M_h)*log2e.
// (launch index 2)
// ============================================================
__global__ void __launch_bounds__(256) bias_kernel(const float* __restrict__ ls)
{
    __shared__ float mh[NH_];
    if (threadIdx.x < NH_)
        mh[threadIdx.x] = __expf(fminf(ls[threadIdx.x], 4.6051702f)) + 16.f;
    __syncthreads();

    int n = blockIdx.x;                       // query
    int m = blockIdx.y * 256 + threadIdx.x;   // key
    int i = n >> 5, j = n & 31;
    int p = m >> 5, q = m & 31;
    int idx = (i - p + 31) * 63 + (j - q + 31);
    const float* t = g_tab + idx * NH_;
    #pragma unroll
    for (int h = 0; h < NH_; h++) {
        float v = 16.f / (1.f + __expf(-t[h]));
        g_biasH[((size_t)h * N_ + n) * N_ + m] =
            __float2half_rn((v - mh[h]) * 1.44269504f);
    }
}

// ============================================================
// K_qkvgemm: R10 configuration (best measured: 45 us).
// (launch index 3 — ncu slot)
// ============================================================
__global__ void __launch_bounds__(256) qkvgemm_kernel(
    const float* __restrict__ x,
    const float* __restrict__ q1b, const float* __restrict__ q2b,
    const float* __restrict__ k1b, const float* __restrict__ k2b,
    const float* __restrict__ v1b, const float* __restrict__ v2b)
{
    __shared__ __align__(16) __nv_bfloat16 xh_s[128][72];
    __shared__ __align__(16) __nv_bfloat16 xl_s[128][72];

    const int tid  = threadIdx.x;
    const int lane = tid & 31;
    const int w    = tid >> 5;
    const int b    = blockIdx.y;
    const int tok0 = blockIdx.x * 64;
    const int r0   = w * 16 + (lane >> 2);
    const int fc2  = 2 * (lane & 3);

    const u32 xh0 = smem_u32(&xh_s[0][0]);
    const u32 xl0 = smem_u32(&xl_s[0][0]);
    const u32 lmoff = (u32)((((lane & 7) + ((lane >> 3) & 1) * 8) * 144)
                            + ((lane >> 4) & 1) * 16);

    const float* Bss[6] = {q1b, q2b, k1b, k2b, v1b, v2b};
    float* Outs[3] = {g_q, g_k, g_v};

    for (int half = 0; half < 2; half++) {
        __syncthreads();
        #pragma unroll
        for (int r = 0; r < 8; r++) {
            int idx = r * 256 + tid;
            int ch = idx >> 4, t4 = (idx & 15) * 4;
            float4 xv = *(const float4*)&x[((size_t)(b * 256 + half * 128 + ch) << 10) + tok0 + t4];
            u32 hw0, lw0, hw1, lw1;
            split2(xv.x, xv.y, hw0, lw0);
            split2(xv.z, xv.w, hw1, lw1);
            *(uint2*)&xh_s[ch][t4] = make_uint2(hw0, hw1);
            *(uint2*)&xl_s[ch][t4] = make_uint2(lw0, lw1);
        }
        __syncthreads();

        for (int g = 0; g < 3; g++) {
            const int m = g * 2 + half;
            const uint4* wf = (const uint4*)g_wfrag + ((size_t)(m * 8 + w) * 24) * 32 + lane;

            float c[8][4];
            #pragma unroll
            for (int i = 0; i < 8; i++) { c[i][0] = c[i][1] = c[i][2] = c[i][3] = 0.f; }

            #pragma unroll 4
            for (int ks = 0; ks < 24; ks++) {
                uint4 aa = __ldg(&wf[ks * 32]);   // coalesced LDG.128
                u32 bb = ((ks < 16) ? xh0 : xl0) + (u32)((ks & 7) * 16 * 144) + lmoff;
                #pragma unroll
                for (int nt = 0; nt < 4; nt++) {
                    u32 f0, f1, f2, f3;
                    LDSM_X4_T(f0, f1, f2, f3, bb + nt * 32);
                    MMA16816(c[2*nt][0], c[2*nt][1], c[2*nt][2], c[2*nt][3],
                             aa.x, aa.y, aa.z, aa.w, f0, f1);
                    MMA16816(c[2*nt+1][0], c[2*nt+1][1], c[2*nt+1][2], c[2*nt+1][3],
                             aa.x, aa.y, aa.z, aa.w, f2, f3);
                }
            }

            float bb0 = __ldg(&Bss[m][r0]);
            float bb1 = __ldg(&Bss[m][r0 + 8]);
            const float* xr = x + ((size_t)(b * 256 + half * 128) << 10);
            float* op = Outs[g] + ((size_t)(b * 256 + half * 128) << 10);
            #pragma unroll
            for (int n8 = 0; n8 < 8; n8++) {
                int tok = tok0 + n8 * 8 + fc2;
                float2 rx0 = *(const float2*)&xr[((size_t)r0 << 10) + tok];
                float2 rx1 = *(const float2*)&xr[((size_t)(r0 + 8) << 10) + tok];
                float2 o0 = make_float2(c[n8][0] + rx0.x + bb0, c[n8][1] + rx0.y + bb0);
                float2 o1 = make_float2(c[n8][2] + rx1.x + bb1, c[n8][3] + rx1.y + bb1);
                *(float2*)&op[((size_t)r0 << 10) + tok] = o0;
                *(float2*)&op[((size_t)(r0 + 8) << 10) + tok] = o1;
            }
        }
    }
}

// ============================================================
// K_normsplit (launch index 4)
// ============================================================
__global__ void __launch_bounds__(128) normsplit_kernel()
{
    __shared__ float xs[32][129];
    __shared__ u32 os[128][49];

    const int tid = threadIdx.x;
    const int chunk = blockIdx.x, bh = blockIdx.y, qk = blockIdx.z;
    const int b = bh >> 3, h = bh & 7;
    const int tok0 = chunk * 128;
    const float* src = (qk ? g_k : g_q) + ((size_t)(b * 256 + h * 32) << 10) + tok0;

    #pragma unroll
    for (int r = 0; r < 8; r++) {
        int idx = r * 128 + tid;
        int ch = idx >> 5, t4 = (idx & 31) * 4;
        float4 v = *(const float4*)&src[((size_t)ch << 10) + t4];
        xs[ch][t4] = v.x; xs[ch][t4+1] = v.y; xs[ch][t4+2] = v.z; xs[ch][t4+3] = v.w;
    }
    __syncthreads();

    float vals[32]; float s = 0.f;
    #pragma unroll
    for (int ch = 0; ch < 32; ch++) { vals[ch] = xs[ch][tid]; s += vals[ch] * vals[ch]; }
    float inv = 1.f / fmaxf(sqrtf(s), 1e-12f);

    #pragma unroll
    for (int j = 0; j < 16; j++) {
        float v0 = vals[2*j] * inv, v1 = vals[2*j+1] * inv;
        u32 hh, ll;
        split2(v0, v1, hh, ll);
        if (qk == 0) { os[tid][j] = hh; os[tid][16+j] = ll; os[tid][32+j] = hh; }
        else         { os[tid][j] = hh; os[tid][16+j] = hh; os[tid][32+j] = ll; }
    }
    __syncthreads();

    __nv_bfloat16* dst = (qk ? g_ks : g_qs) + ((size_t)bh * N_ + tok0) * 96;
    #pragma unroll
    for (int r = 0; r < 12; r++) {
        int idx = r * 128 + tid;
        int row = idx / 12, seg = idx % 12;
        uint4 v = make_uint4(os[row][seg*4], os[row][seg*4+1],
                             os[row][seg*4+2], os[row][seg*4+3]);
        *(uint4*)(dst + (size_t)row * 96 + seg * 8) = v;
    }
}

// ============================================================
// K_vsplit: v [b][c][tok] -> g_vt [bh][vh|vl][tok]. (launch index 5)
// ============================================================
__global__ void __launch_bounds__(256) vsplit_kernel()
{
    const int row = blockIdx.x;            // b*256 + c
    const int b = row >> 8, c = row & 255;
    const int h = c >> 5, d = c & 31;
    const float* src = g_v + ((size_t)row << 10);
    __nv_bfloat16* dh = g_vt + (((size_t)(b * 8 + h)) * 64 + d) * 1024;
    __nv_bfloat16* dl = dh + 32 * 1024;
    int t4 = threadIdx.x * 4;
    float4 v = *(const float4*)&src[t4];
    u32 hw0, lw0, hw1, lw1;
    split2(v.x, v.y, hw0, lw0);
    split2(v.z, v.w, hw1, lw1);
    *(uint2*)&dh[t4] = make_uint2(hw0, hw1);
    *(uint2*)&dl[t4] = make_uint2(lw0, lw1);
}

// ============================================================
// K4: attention — chunked softmax, fp16 bias, ex2. (launch index 6)
// ============================================================
__global__ void __launch_bounds__(256, 2) attn_kernel(const float* __restrict__ logit_scale)
{
    __shared__ __align__(16) __nv_bfloat16 ks_s[2][64][104];
    __shared__ __align__(16) __nv_bfloat16 vt_s[2][64][72];

    const int tid  = threadIdx.x;
    const int lane = tid & 31;
    const int w    = tid >> 5;
    const int bh   = blockIdx.y;
    const int h    = bh & 7;
    const int q0   = blockIdx.x * 128;
    const int qr   = q0 + w * 16 + (lane >> 2);
    const int fc2  = 2 * (lane & 3);

    // K-ext layout [qh|ql|qh]: ksteps 4,5 duplicate 0,1 -> load 4 only
    u32 aQ[4][4];
    {
        const __nv_bfloat16* qb = g_qs + ((size_t)bh * N_ + qr) * 96;
        #pragma unroll
        for (int ks = 0; ks < 4; ks++) {
            int f = fc2 + 16 * ks;
            aQ[ks][0] = *(const u32*)(qb + f);
            aQ[ks][1] = *(const u32*)(qb + 8 * 96 + f);
            aQ[ks][2] = *(const u32*)(qb + f + 8);
            aQ[ks][3] = *(const u32*)(qb + 8 * 96 + f + 8);
        }
    }

    const float scale = __expf(fminf(logit_scale[h], 4.6051702f));
    const float sl2e  = scale * 1.44269504f;

    float o[4][4];
    #pragma unroll
    for (int i = 0; i < 4; i++)
        #pragma unroll
        for (int j = 0; j < 4; j++) o[i][j] = 0.f;
    float s0 = 0.f, s1 = 0.f;

    const __half* bias0 = g_biasH + ((size_t)h * N_ + qr) * N_;
    const __half* bias1 = bias0 + (size_t)8 * N_;

    const u32 ks0 = smem_u32(&ks_s[0][0][0]);
    const u32 vt0 = smem_u32(&vt_s[0][0][0]);
    const u32 KSB = 64 * 104 * 2;
    const u32 VTB = 64 * 72 * 2;

    const u32 lmK = (u32)(((((lane >> 4) & 1) * 8 + (lane & 7)) * 104
                           + ((lane >> 3) & 1) * 8) * 2);
    const u32 lmV = (u32)(((((lane >> 4) & 1) * 32 + (lane & 7)) * 72
                           + ((lane >> 3) & 1) * 8) * 2);

    const char* kgbase = (const char*)(g_ks + (size_t)bh * N_ * 96);
    const char* vgbase = (const char*)(g_vt + (size_t)bh * 64 * N_);

    auto stage = [&](int kt, int bf) {
        const char* src = kgbase + (size_t)kt * 64 * 192;
        u32 dst = ks0 + bf * KSB;
        #pragma unroll
        for (int i = 0; i < 3; i++) {
            int idx = i * 256 + tid;
            int key = idx / 12, seg = idx % 12;
            CP_ASYNC16(dst + (key * 104 + seg * 8) * 2, src + key * 192 + seg * 16);
        }
        const char* vs = vgbase + (size_t)kt * 64 * 2;
        u32 vdst = vt0 + bf * VTB;
        #pragma unroll
        for (int i = 0; i < 2; i++) {
            int idx = i * 256 + tid;
            int f = idx / 8, seg = idx % 8;
            CP_ASYNC16(vdst + (f * 72 + seg * 8) * 2, vs + (size_t)f * N_ * 2 + seg * 16);
        }
        CP_COMMIT();
    };

    stage(0, 0);

    for (int kt = 0; kt < 16; kt++) {
        const int buf = kt & 1;
        CP_WAIT0();
        __syncthreads();
        if (kt < 15) stage(kt + 1, buf ^ 1);

        const u32 kbase = ks0 + buf * KSB;
        const u32 vbase = vt0 + buf * VTB;

        #pragma unroll
        for (int kc = 0; kc < 4; kc++) {
            // ---- QK^T for 16 keys ----
            float c[2][4];
            c[0][0] = c[0][1] = c[0][2] = c[0][3] = 0.f;
            c[1][0] = c[1][1] = c[1][2] = c[1][3] = 0.f;
            #pragma unroll
            for (int ks = 0; ks < 6; ks++) {
                const int qi = (ks < 4) ? ks : ks - 4;
                u32 b00, b01, b10, b11;
                LDSM_X4(b00, b01, b10, b11,
                        kbase + lmK + (u32)((kc * 16 * 104 + 16 * ks) * 2));
                MMA16816(c[0][0], c[0][1], c[0][2], c[0][3],
                         aQ[qi][0], aQ[qi][1], aQ[qi][2], aQ[qi][3], b00, b01);
                MMA16816(c[1][0], c[1][1], c[1][2], c[1][3],
                         aQ[qi][0], aQ[qi][1], aQ[qi][2], aQ[qi][3], b10, b11);
            }

            // ---- softmax slice (fp16 bias pre-scaled by log2e, M folded) ----
            int kg = kt * 64 + kc * 16 + fc2;
            float2 bb0 = __half22float2(*(const __half2*)(bias0 + kg));
            float2 bb1 = __half22float2(*(const __half2*)(bias1 + kg));
            float2 bb2 = __half22float2(*(const __half2*)(bias0 + kg + 8));
            float2 bb3 = __half22float2(*(const __half2*)(bias1 + kg + 8));
            float pv0 = ex2(fmaf(c[0][0], sl2e, bb0.x));
            float pv1 = ex2(fmaf(c[0][1], sl2e, bb0.y));
            float pv2 = ex2(fmaf(c[0][2], sl2e, bb1.x));
            float pv3 = ex2(fmaf(c[0][3], sl2e, bb1.y));
            float pw0 = ex2(fmaf(c[1][0], sl2e, bb2.x));
            float pw1 = ex2(fmaf(c[1][1], sl2e, bb2.y));
            float pw2 = ex2(fmaf(c[1][2], sl2e, bb3.x));
            float pw3 = ex2(fmaf(c[1][3], sl2e, bb3.y));
            s0 += (pv0 + pv1) + (pw0 + pw1);
            s1 += (pv2 + pv3) + (pw2 + pw3);

            u32 aPh[4], aPl[4];
            split2(pv0, pv1, aPh[0], aPl[0]);
            split2(pv2, pv3, aPh[1], aPl[1]);
            split2(pw0, pw1, aPh[2], aPl[2]);
            split2(pw2, pw3, aPh[3], aPl[3]);

            // ---- P·V for these 16 keys ----
            #pragma unroll
            for (int nt = 0; nt < 4; nt++) {
                u32 bh0, bh1, bl0, bl1;
                LDSM_X4(bh0, bh1, bl0, bl1,
                        vbase + lmV + (u32)((nt * 8 * 72 + 16 * kc) * 2));
                MMA16816(o[nt][0], o[nt][1], o[nt][2], o[nt][3],
                         aPh[0], aPh[1], aPh[2], aPh[3], bh0, bh1);
                MMA16816(o[nt][0], o[nt][1], o[nt][2], o[nt][3],
                         aPl[0], aPl[1], aPl[2], aPl[3], bh0, bh1);
                MMA16816(o[nt][0], o[nt][1], o[nt][2], o[nt][3],
                         aPh[0], aPh[1], aPh[2], aPh[3], bl0, bl1);
            }
        }
    }

    s0 += __shfl_xor_sync(0xffffffffu, s0, 1);
    s0 += __shfl_xor_sync(0xffffffffu, s0, 2);
    s1 += __shfl_xor_sync(0xffffffffu, s1, 1);
    s1 += __shfl_xor_sync(0xffffffffu, s1, 2);
    float i0 = 1.f / s0, i1 = 1.f / s1;

    #pragma unroll
    for (int nt = 0; nt < 4; nt++) {
        int dd = nt * 8 + fc2;
        float2 w0 = make_float2(o[nt][0] * i0, o[nt][1] * i0);
        float2 w1 = make_float2(o[nt][2] * i1, o[nt][3] * i1);
        *(float2*)&g_o[((size_t)bh * N_ + qr) * HD_ + dd]     = w0;
        *(float2*)&g_o[((size_t)bh * N_ + qr + 8) * HD_ + dd] = w1;
    }
}

// ============================================================
// K_osplit: g_o [bh][tok][d] -> channel-major bf16 splits.
// (launch index 7)
// ============================================================
__global__ void __launch_bounds__(256) osplit_kernel()
{
    __shared__ float ts[32][130];
    const int tid = threadIdx.x;
    const int chunk = blockIdx.x, bh = blockIdx.y;
    const int b = bh >> 3, h = bh & 7;
    const int tok0 = chunk * 128;
    const float* src = g_o + ((size_t)(bh * 1024 + tok0)) * 32;

    #pragma unroll
    for (int r = 0; r < 4; r++) {
        int idx = r * 256 + tid;
        int tok = idx >> 3, d4 = (idx & 7) * 4;
        float4 v = *(const float4*)&src[tok * 32 + d4];
        ts[d4][tok] = v.x; ts[d4+1][tok] = v.y; ts[d4+2][tok] = v.z; ts[d4+3][tok] = v.w;
    }
    __syncthreads();

    const int d = tid >> 3, seg = tid & 7;
    u32 hh[8], ll[8];
    #pragma unroll
    for (int i = 0; i < 8; i++) {
        float v0 = ts[d][seg * 16 + 2*i];
        float v1 = ts[d][seg * 16 + 2*i + 1];
        split2(v0, v1, hh[i], ll[i]);
    }
    size_t off = ((size_t)(b * 256 + h * 32 + d) << 10) + tok0 + seg * 16;
    *(uint4*)&g_osh[off]     = make_uint4(hh[0], hh[1], hh[2], hh[3]);
    *(uint4*)&g_osh[off + 8] = make_uint4(hh[4], hh[5], hh[6], hh[7]);
    *(uint4*)&g_osl[off]     = make_uint4(ll[0], ll[1], ll[2], ll[3]);
    *(uint4*)&g_osl[off + 8] = make_uint4(ll[4], ll[5], ll[6], ll[7]);
}

// ============================================================
// K_projgemm: output projection, 64-token tiles. (launch index 8)
// ============================================================
__global__ void __launch_bounds__(256) projgemm_kernel(
    const float* __restrict__ p1b, const float* __restrict__ p2b,
    float* __restrict__ out)
{
    __shared__ __align__(16) __nv_bfloat16 xh_s[128][72];
    __shared__ __align__(16) __nv_bfloat16 xl_s[128][72];

    const int tid  = threadIdx.x;
    const int lane = tid & 31;
    const int w    = tid >> 5;
    const int b    = blockIdx.y;
    const int tok0 = blockIdx.x * 64;
    const int r0   = w * 16 + (lane >> 2);
    const int fc2  = 2 * (lane & 3);

    const u32 xh0 = smem_u32(&xh_s[0][0]);
    const u32 xl0 = smem_u32(&xl_s[0][0]);
    const u32 lmoff = (u32)((((lane & 7) + ((lane >> 3) & 1) * 8) * 144)
                            + ((lane >> 4) & 1) * 16);

    const float* Bss[2] = {p1b, p2b};

    for (int half = 0; half < 2; half++) {
        __syncthreads();
        {
            const char* sh = (const char*)g_osh
                + (((size_t)(b * 256 + half * 128) << 10) + tok0) * 2;
            const char* sl = (const char*)g_osl
                + (((size_t)(b * 256 + half * 128) << 10) + tok0) * 2;
            #pragma unroll
            for (int r = 0; r < 4; r++) {
                int idx = r * 256 + tid;
                int ch = idx >> 3, seg = idx & 7;
                CP_ASYNC16(xh0 + (ch * 72 + seg * 8) * 2, sh + ((size_t)ch << 11) + seg * 16);
                CP_ASYNC16(xl0 + (ch * 72 + seg * 8) * 2, sl + ((size_t)ch << 11) + seg * 16);
            }
            CP_COMMIT(); CP_WAIT0();
        }
        __syncthreads();

        const int m = 6 + half;
        const uint4* wf = (const uint4*)g_wfrag + ((size_t)(m * 8 + w) * 24) * 32 + lane;

        float c[8][4];
        #pragma unroll
        for (int i = 0; i < 8; i++) { c[i][0] = c[i][1] = c[i][2] = c[i][3] = 0.f; }

        #pragma unroll 4
        for (int ks = 0; ks < 24; ks++) {
            uint4 aa = __ldg(&wf[ks * 32]);
            u32 bb = ((ks < 16) ? xh0 : xl0) + (u32)((ks & 7) * 16 * 144) + lmoff;
            #pragma unroll
            for (int nt = 0; nt < 4; nt++) {
                u32 f0, f1, f2, f3;
                LDSM_X4_T(f0, f1, f2, f3, bb + nt * 32);
                MMA16816(c[2*nt][0], c[2*nt][1], c[2*nt][2], c[2*nt][3],
                         aa.x, aa.y, aa.z, aa.w, f0, f1);
                MMA16816(c[2*nt+1][0], c[2*nt+1][1], c[2*nt+1][2], c[2*nt+1][3],
                         aa.x, aa.y, aa.z, aa.w, f2, f3);
            }
        }

        float bb0 = __ldg(&Bss[half][r0]);
        float bb1 = __ldg(&Bss[half][r0 + 8]);
        float* op = out + ((size_t)(b * 256 + half * 128) << 10);
        #pragma unroll
        for (int n8 = 0; n8 < 8; n8++) {
            int tok = tok0 + n8 * 8 + fc2;
            float2 o0 = make_float2(c[n8][0] + bb0, c[n8][1] + bb0);
            float2 o1 = make_float2(c[n8][2] + bb1, c[n8][3] + bb1);
            *(float2*)&op[((size_t)r0 << 10) + tok] = o0;
            *(float2*)&op[((size_t)(r0 + 8) << 10) + tok] = o1;
        }
    }
}

// ============================================================
extern "C" void kernel_launch(void* const* d_in, const int* in_sizes, int n_in,
                              void* d_out, int out_size)
{
    const float* x    = (const float*)d_in[0];
    const float* q1w  = (const float*)d_in[1];
    const float* q1b  = (const float*)d_in[2];
    const float* q2w  = (const float*)d_in[3];
    const float* q2b  = (const float*)d_in[4];
    const float* k1w  = (const float*)d_in[5];
    const float* k1b  = (const float*)d_in[6];
    const float* k2w  = (const float*)d_in[7];
    const float* k2b  = (const float*)d_in[8];
    const float* v1w  = (const float*)d_in[9];
    const float* v1b  = (const float*)d_in[10];
    const float* v2w  = (const float*)d_in[11];
    const float* v2b  = (const float*)d_in[12];
    const float* p1w  = (const float*)d_in[13];
    const float* p1b  = (const float*)d_in[14];
    const float* p2w  = (const float*)d_in[15];
    const float* p2b  = (const float*)d_in[16];
    const float* ls   = (const float*)d_in[17];
    const float* m1w  = (const float*)d_in[18];
    const float* m1b  = (const float*)d_in[19];
    const float* m2w  = (const float*)d_in[20];
    float* out = (float*)d_out;

    // qkvgemm sits at app-launch index 3 (the ncu slot).
    wext_kernel<<<768, 256>>>(q1w, q2w, k1w, k2w, v1w, v2w, p1w, p2w);
    tab_kernel<<<(TABN_ + 255) / 256, 256>>>(m1w, m1b, m2w);
    bias_kernel<<<dim3(N_, N_ / 256), 256>>>(ls);
    qkvgemm_kernel<<<dim3(16, 16), 256>>>(x, q1b, q2b, k1b, k2b, v1b, v2b);
    normsplit_kernel<<<dim3(8, 128, 2), 128>>>();
    vsplit_kernel<<<4096, 256>>>();
    attn_kernel<<<dim3(N_ / 128, BH_), 256>>>(ls);
    osplit_kernel<<<dim3(8, 128), 256>>>();
    projgemm_kernel<<<dim3(16, 16), 256>>>(p1b, p2b, out);
}

// round 17
// speedup vs baseline: 1.2249x; 1.1011x over previous
#include <cuda_runtime.h>
#include <cuda_bf16.h>
#include <cuda_fp16.h>
#include <math.h>
#include <stdint.h>

#define B_    16
#define C_    256
#define N_    1024      // 32*32 tokens
#define NH_   8
#define HD_   32
#define HALF_ 128
#define BH_   (B_*NH_)  // 128
#define TABN_ 3969      // 63*63

typedef unsigned long long u64;
typedef unsigned int u32;

// bf16 mma m16n8k16, fp32 accum
#define MMA16816(d0,d1,d2,d3,a0,a1,a2,a3,b0,b1) \
    asm("mma.sync.aligned.m16n8k16.row.col.f32.bf16.bf16.f32 " \
        "{%0,%1,%2,%3}, {%4,%5,%6,%7}, {%8,%9}, {%0,%1,%2,%3};" \
        : "+f"(d0), "+f"(d1), "+f"(d2), "+f"(d3) \
        : "r"(a0), "r"(a1), "r"(a2), "r"(a3), "r"(b0), "r"(b1))

// fp16 mma m16n8k16, fp32 accum (attention QK)
#define MMAF16(d0,d1,d2,d3,a0,a1,a2,a3,b0,b1) \
    asm("mma.sync.aligned.m16n8k16.row.col.f32.f16.f16.f32 " \
        "{%0,%1,%2,%3}, {%4,%5,%6,%7}, {%8,%9}, {%0,%1,%2,%3};" \
        : "+f"(d0), "+f"(d1), "+f"(d2), "+f"(d3) \
        : "r"(a0), "r"(a1), "r"(a2), "r"(a3), "r"(b0), "r"(b1))

#define LDSM_X4(r0,r1,r2,r3,addr) \
    asm volatile("ldmatrix.sync.aligned.m8n8.x4.shared.b16 {%0,%1,%2,%3}, [%4];" \
        : "=r"(r0), "=r"(r1), "=r"(r2), "=r"(r3) : "r"(addr))

#define LDSM_X4_T(r0,r1,r2,r3,addr) \
    asm volatile("ldmatrix.sync.aligned.m8n8.x4.trans.shared.b16 {%0,%1,%2,%3}, [%4];" \
        : "=r"(r0), "=r"(r1), "=r"(r2), "=r"(r3) : "r"(addr))

#define CP_ASYNC16(dst,src) \
    asm volatile("cp.async.cg.shared.global [%0], [%1], 16;" :: "r"(dst), "l"(src))
#define CP_COMMIT() asm volatile("cp.async.commit_group;")
#define CP_WAIT0()  asm volatile("cp.async.wait_group 0;")

// guaranteed single-MUFU exp2
__device__ __forceinline__ float ex2(float x) {
    float r;
    asm("ex2.approx.f32 %0, %1;" : "=f"(r) : "f"(x));
    return r;
}

__device__ __forceinline__ u32 smem_u32(const void* p) {
    u32 a;
    asm("{ .reg .u64 t; cvta.to.shared.u64 t, %1; cvt.u32.u64 %0, t; }"
        : "=r"(a) : "l"(p));
    return a;
}

// ---- scratch (device globals; no runtime allocation allowed) ----
__device__ float g_q[B_*C_*N_];             // 16 MB, [b][c][tok]
__device__ float g_k[B_*C_*N_];             // 16 MB
__device__ float g_v[B_*C_*N_];             // 16 MB
__device__ u32 g_wfrag[8*8*24*32*4];        // pre-swizzled A-fragments (qkv+proj)
__device__ __half g_qs[BH_*N_*64];          // [qh|ql]  fp16, 16 MB
__device__ __half g_ks[BH_*N_*64];          // [kh|kh]  fp16, 16 MB
__device__ __nv_bfloat16 g_vt[BH_*64*N_];   // [bh][vh(32)|vl(32)][key] bf16, 16 MB
__device__ float g_o[BH_*N_*HD_];           // 16 MB
__device__ __nv_bfloat16 g_osh[B_*C_*N_];   // attn out, high split, [b][c][tok]
__device__ __nv_bfloat16 g_osl[B_*C_*N_];   // low split
__device__ float g_tab[TABN_*NH_];
__device__ __half g_biasH[NH_*N_*N_];       // 16 MB, [h][query][key], (b-M)*log2e

__device__ __forceinline__ u32 pkh(__nv_bfloat16 a, __nv_bfloat16 b) {
    __nv_bfloat162 t; t.x = a; t.y = b;
    return *(u32*)&t;
}
__device__ __forceinline__ u32 pkf(float a, float b) {
    __nv_bfloat162 t = __floats2bfloat162_rn(a, b);
    return *(u32*)&t;
}
// split (v0,v1) into packed bf16x2 high + low words (low lane = v0)
__device__ __forceinline__ void split2(float v0, float v1, u32& hw, u32& lw) {
    asm("cvt.rn.bf16x2.f32 %0, %1, %2;" : "=r"(hw) : "f"(v1), "f"(v0));
    float h0 = __uint_as_float(hw << 16);
    float h1 = __uint_as_float(hw & 0xffff0000u);
    float l0 = v0 - h0, l1 = v1 - h1;
    asm("cvt.rn.bf16x2.f32 %0, %1, %2;" : "=r"(lw) : "f"(l1), "f"(l0));
}
// fp16 split
__device__ __forceinline__ void split2h(float v0, float v1, u32& hw, u32& lw) {
    __half2 h = __floats2half2_rn(v0, v1);
    hw = *(u32*)&h;
    float2 hf = __half22float2(h);
    __half2 l = __floats2half2_rn(v0 - hf.x, v1 - hf.y);
    lw = *(u32*)&l;
}

// ============================================================
// K_wext: pre-swizzled split-weight A-fragments, K-ext [wh|wl|wh].
// (launch index 0)
// ============================================================
__global__ void __launch_bounds__(256) wext_kernel(
    const float* __restrict__ q1w, const float* __restrict__ q2w,
    const float* __restrict__ k1w, const float* __restrict__ k2w,
    const float* __restrict__ v1w, const float* __restrict__ v2w,
    const float* __restrict__ p1w, const float* __restrict__ p2w)
{
    const float* Ws[8] = {q1w, q2w, k1w, k2w, v1w, v2w, p1w, p2w};
    int id = blockIdx.x * 256 + threadIdx.x;   // 0..196607
    int j    = id & 3;
    int lane = (id >> 2) & 31;
    int ks   = (id >> 7) % 24;
    int rbm  = id / (128 * 24);
    int rb = rbm & 7, m = rbm >> 3;
    int row = rb * 16 + (lane >> 2) + (j & 1) * 8;
    int col = ks * 16 + 2 * (lane & 3) + ((j >> 1) & 1) * 8;
    int region = col >> 7, ic = col & 127;
    const float* W = Ws[m];
    float v0 = W[row * 128 + ic], v1 = W[row * 128 + ic + 1];
    u32 r;
    if (region == 1) {
        __nv_bfloat16 h0 = __float2bfloat16(v0), h1 = __float2bfloat16(v1);
        r = pkf(v0 - __bfloat162float(h0), v1 - __bfloat162float(h1));
    } else {
        r = pkh(__float2bfloat16(v0), __float2bfloat16(v1));
    }
    g_wfrag[id] = r;
}

// ============================================================
// K2: CPB table MLP (launch index 1)
// ============================================================
__global__ void __launch_bounds__(256) tab_kernel(
    const float* __restrict__ w1, const float* __restrict__ b1,
    const float* __restrict__ w2)
{
    __shared__ float w1s[256];
    __shared__ float b1s[128];
    __shared__ float w2s[1024];
    int tid = threadIdx.x;
    if (tid < 256) w1s[tid] = w1[tid];
    if (tid < 128) b1s[tid] = b1[tid];
    for (int i = tid; i < 1024; i += 256) w2s[i] = w2[i];
    __syncthreads();

    int p = blockIdx.x * 256 + tid;
    if (p >= TABN_) return;
    int a = p / 63, b = p % 63;
    float t0 = ((float)(a - 31) / 31.0f) * 3.2f;
    float t1 = ((float)(b - 31) / 31.0f) * 3.2f;
    t0 = copysignf(1.f - __expf(-fabsf(t0)), t0);
    t1 = copysignf(1.f - __expf(-fabsf(t1)), t1);

    float acc[NH_];
    #pragma unroll
    for (int h = 0; h < NH_; h++) acc[h] = 0.f;
    for (int k = 0; k < 128; k++) {
        float hv = fmaxf(w1s[2 * k] * t0 + w1s[2 * k + 1] * t1 + b1s[k], 0.f);
        #pragma unroll
        for (int h = 0; h < NH_; h++) acc[h] += w2s[h * 128 + k] * hv;
    }
    #pragma unroll
    for (int h = 0; h < NH_; h++) g_tab[p * NH_ + h] = acc[h];
}

// ============================================================
// K3: expand bias to fp16, pre-scaled (bias - M_h)*log2e.
// (launch index 2)
// ============================================================
__global__ void __launch_bounds__(256) bias_kernel(const float* __restrict__ ls)
{
    __shared__ float mh[NH_];
    if (threadIdx.x < NH_)
        mh[threadIdx.x] = __expf(fminf(ls[threadIdx.x], 4.6051702f)) + 16.f;
    __syncthreads();

    int n = blockIdx.x;                       // query
    int m = blockIdx.y * 256 + threadIdx.x;   // key
    int i = n >> 5, j = n & 31;
    int p = m >> 5, q = m & 31;
    int idx = (i - p + 31) * 63 + (j - q + 31);
    const float* t = g_tab + idx * NH_;
    #pragma unroll
    for (int h = 0; h < NH_; h++) {
        float v = 16.f / (1.f + __expf(-t[h]));
        g_biasH[((size_t)h * N_ + n) * N_ + m] =
            __float2half_rn((v - mh[h]) * 1.44269504f);
    }
}

// ============================================================
// K_qkvgemm: R10 configuration (unchanged, 45 us).
// (launch index 3 — ncu slot)
// ============================================================
__global__ void __launch_bounds__(256) qkvgemm_kernel(
    const float* __restrict__ x,
    const float* __restrict__ q1b, const float* __restrict__ q2b,
    const float* __restrict__ k1b, const float* __restrict__ k2b,
    const float* __restrict__ v1b, const float* __restrict__ v2b)
{
    __shared__ __align__(16) __nv_bfloat16 xh_s[128][72];
    __shared__ __align__(16) __nv_bfloat16 xl_s[128][72];

    const int tid  = threadIdx.x;
    const int lane = tid & 31;
    const int w    = tid >> 5;
    const int b    = blockIdx.y;
    const int tok0 = blockIdx.x * 64;
    const int r0   = w * 16 + (lane >> 2);
    const int fc2  = 2 * (lane & 3);

    const u32 xh0 = smem_u32(&xh_s[0][0]);
    const u32 xl0 = smem_u32(&xl_s[0][0]);
    const u32 lmoff = (u32)((((lane & 7) + ((lane >> 3) & 1) * 8) * 144)
                            + ((lane >> 4) & 1) * 16);

    const float* Bss[6] = {q1b, q2b, k1b, k2b, v1b, v2b};
    float* Outs[3] = {g_q, g_k, g_v};

    for (int half = 0; half < 2; half++) {
        __syncthreads();
        #pragma unroll
        for (int r = 0; r < 8; r++) {
            int idx = r * 256 + tid;
            int ch = idx >> 4, t4 = (idx & 15) * 4;
            float4 xv = *(const float4*)&x[((size_t)(b * 256 + half * 128 + ch) << 10) + tok0 + t4];
            u32 hw0, lw0, hw1, lw1;
            split2(xv.x, xv.y, hw0, lw0);
            split2(xv.z, xv.w, hw1, lw1);
            *(uint2*)&xh_s[ch][t4] = make_uint2(hw0, hw1);
            *(uint2*)&xl_s[ch][t4] = make_uint2(lw0, lw1);
        }
        __syncthreads();

        for (int g = 0; g < 3; g++) {
            const int m = g * 2 + half;
            const uint4* wf = (const uint4*)g_wfrag + ((size_t)(m * 8 + w) * 24) * 32 + lane;

            float c[8][4];
            #pragma unroll
            for (int i = 0; i < 8; i++) { c[i][0] = c[i][1] = c[i][2] = c[i][3] = 0.f; }

            #pragma unroll 4
            for (int ks = 0; ks < 24; ks++) {
                uint4 aa = __ldg(&wf[ks * 32]);   // coalesced LDG.128
                u32 bb = ((ks < 16) ? xh0 : xl0) + (u32)((ks & 7) * 16 * 144) + lmoff;
                #pragma unroll
                for (int nt = 0; nt < 4; nt++) {
                    u32 f0, f1, f2, f3;
                    LDSM_X4_T(f0, f1, f2, f3, bb + nt * 32);
                    MMA16816(c[2*nt][0], c[2*nt][1], c[2*nt][2], c[2*nt][3],
                             aa.x, aa.y, aa.z, aa.w, f0, f1);
                    MMA16816(c[2*nt+1][0], c[2*nt+1][1], c[2*nt+1][2], c[2*nt+1][3],
                             aa.x, aa.y, aa.z, aa.w, f2, f3);
                }
            }

            float bb0 = __ldg(&Bss[m][r0]);
            float bb1 = __ldg(&Bss[m][r0 + 8]);
            const float* xr = x + ((size_t)(b * 256 + half * 128) << 10);
            float* op = Outs[g] + ((size_t)(b * 256 + half * 128) << 10);
            #pragma unroll
            for (int n8 = 0; n8 < 8; n8++) {
                int tok = tok0 + n8 * 8 + fc2;
                float2 rx0 = *(const float2*)&xr[((size_t)r0 << 10) + tok];
                float2 rx1 = *(const float2*)&xr[((size_t)(r0 + 8) << 10) + tok];
                float2 o0 = make_float2(c[n8][0] + rx0.x + bb0, c[n8][1] + rx0.y + bb0);
                float2 o1 = make_float2(c[n8][2] + rx1.x + bb1, c[n8][3] + rx1.y + bb1);
                *(float2*)&op[((size_t)r0 << 10) + tok] = o0;
                *(float2*)&op[((size_t)(r0 + 8) << 10) + tok] = o1;
            }
        }
    }
}

// ============================================================
// K_normsplit: normalize q/k rows, emit fp16 2-seg layouts:
// q: [qh|ql], k: [kh|kh]. 64 halves per row. (launch index 4)
// ============================================================
__global__ void __launch_bounds__(128) normsplit_kernel()
{
    __shared__ float xs[32][129];
    __shared__ u32 os[128][33];

    const int tid = threadIdx.x;
    const int chunk = blockIdx.x, bh = blockIdx.y, qk = blockIdx.z;
    const int b = bh >> 3, h = bh & 7;
    const int tok0 = chunk * 128;
    const float* src = (qk ? g_k : g_q) + ((size_t)(b * 256 + h * 32) << 10) + tok0;

    #pragma unroll
    for (int r = 0; r < 8; r++) {
        int idx = r * 128 + tid;
        int ch = idx >> 5, t4 = (idx & 31) * 4;
        float4 v = *(const float4*)&src[((size_t)ch << 10) + t4];
        xs[ch][t4] = v.x; xs[ch][t4+1] = v.y; xs[ch][t4+2] = v.z; xs[ch][t4+3] = v.w;
    }
    __syncthreads();

    float vals[32]; float s = 0.f;
    #pragma unroll
    for (int ch = 0; ch < 32; ch++) { vals[ch] = xs[ch][tid]; s += vals[ch] * vals[ch]; }
    float inv = 1.f / fmaxf(sqrtf(s), 1e-12f);

    #pragma unroll
    for (int j = 0; j < 16; j++) {
        float v0 = vals[2*j] * inv, v1 = vals[2*j+1] * inv;
        u32 hh, ll;
        split2h(v0, v1, hh, ll);
        if (qk == 0) { os[tid][j] = hh; os[tid][16+j] = ll; }   // [qh|ql]
        else         { os[tid][j] = hh; os[tid][16+j] = hh; }   // [kh|kh]
    }
    __syncthreads();

    __half* dst = (qk ? g_ks : g_qs) + ((size_t)bh * N_ + tok0) * 64;
    #pragma unroll
    for (int r = 0; r < 8; r++) {
        int idx = r * 128 + tid;       // 0..1023 uint4
        int row = idx >> 3, seg = idx & 7;
        uint4 v = make_uint4(os[row][seg*4], os[row][seg*4+1],
                             os[row][seg*4+2], os[row][seg*4+3]);
        *(uint4*)(dst + (size_t)row * 64 + seg * 8) = v;
    }
}

// ============================================================
// K_vsplit: v [b][c][tok] -> g_vt bf16 [bh][vh|vl][tok] (R14 proven).
// (launch index 5)
// ============================================================
__global__ void __launch_bounds__(256) vsplit_kernel()
{
    const int row = blockIdx.x;            // b*256 + c
    const int b = row >> 8, c = row & 255;
    const int h = c >> 5, d = c & 31;
    const float* src = g_v + ((size_t)row << 10);
    __nv_bfloat16* dh = g_vt + (((size_t)(b * 8 + h)) * 64 + d) * 1024;
    __nv_bfloat16* dl = dh + 32 * 1024;
    int t4 = threadIdx.x * 4;
    float4 v = *(const float4*)&src[t4];
    u32 hw0, lw0, hw1, lw1;
    split2(v.x, v.y, hw0, lw0);
    split2(v.z, v.w, hw1, lw1);
    *(uint2*)&dh[t4] = make_uint2(hw0, hw1);
    *(uint2*)&dl[t4] = make_uint2(lw0, lw1);
}

// ============================================================
// K4: attention — QK fp16 2-term (empirically ~1e-4 error) +
// PV bf16 3-term (R14 proven). Chunked softmax, fp16 bias, ex2.
// (launch index 6)
// ============================================================
__global__ void __launch_bounds__(256, 2) attn_kernel(const float* __restrict__ logit_scale)
{
    __shared__ __align__(16) __half        ks_s[2][64][72];   // 2 x 9 KB (fp16)
    __shared__ __align__(16) __nv_bfloat16 vt_s[2][64][72];   // 2 x 9 KB (bf16 vh|vl)

    const int tid  = threadIdx.x;
    const int lane = tid & 31;
    const int w    = tid >> 5;
    const int bh   = blockIdx.y;
    const int h    = bh & 7;
    const int q0   = blockIdx.x * 128;
    const int qr   = q0 + w * 16 + (lane >> 2);
    const int fc2  = 2 * (lane & 3);

    // Q A-fragments: 4 ksteps over [qh(32)|ql(32)] fp16
    u32 aQ[4][4];
    {
        const __half* qb = g_qs + ((size_t)bh * N_ + qr) * 64;
        #pragma unroll
        for (int ks = 0; ks < 4; ks++) {
            int f = fc2 + 16 * ks;
            aQ[ks][0] = *(const u32*)(qb + f);
            aQ[ks][1] = *(const u32*)(qb + 8 * 64 + f);
            aQ[ks][2] = *(const u32*)(qb + f + 8);
            aQ[ks][3] = *(const u32*)(qb + 8 * 64 + f + 8);
        }
    }

    const float scale = __expf(fminf(logit_scale[h], 4.6051702f));
    const float sl2e  = scale * 1.44269504f;

    float o[4][4];
    #pragma unroll
    for (int i = 0; i < 4; i++)
        #pragma unroll
        for (int j = 0; j < 4; j++) o[i][j] = 0.f;
    float s0 = 0.f, s1 = 0.f;

    const __half* bias0 = g_biasH + ((size_t)h * N_ + qr) * N_;
    const __half* bias1 = bias0 + (size_t)8 * N_;

    const u32 ks0 = smem_u32(&ks_s[0][0][0]);
    const u32 vt0 = smem_u32(&vt_s[0][0][0]);
    const u32 KSB = 64 * 72 * 2;   // 9216
    const u32 VTB = 64 * 72 * 2;   // 9216

    const u32 lmK = (u32)(((((lane >> 4) & 1) * 8 + (lane & 7)) * 72
                           + ((lane >> 3) & 1) * 8) * 2);
    const u32 lmV = (u32)(((((lane >> 4) & 1) * 32 + (lane & 7)) * 72
                           + ((lane >> 3) & 1) * 8) * 2);

    const char* kgbase = (const char*)(g_ks + (size_t)bh * N_ * 64);
    const char* vgbase = (const char*)(g_vt + (size_t)bh * 64 * N_);

    auto stage = [&](int kt, int bf) {
        const char* src = kgbase + (size_t)kt * 64 * 128;   // 64 halves = 128B/row
        u32 dst = ks0 + bf * KSB;
        #pragma unroll
        for (int i = 0; i < 2; i++) {
            int idx = i * 256 + tid;          // 0..511
            int key = idx >> 3, seg = idx & 7;
            CP_ASYNC16(dst + (key * 72 + seg * 8) * 2, src + key * 128 + seg * 16);
        }
        const char* vs = vgbase + (size_t)kt * 128;   // 64 keys * 2B
        u32 vdst = vt0 + bf * VTB;
        #pragma unroll
        for (int i = 0; i < 2; i++) {
            int idx = i * 256 + tid;          // 0..511
            int f = idx >> 3, seg = idx & 7;  // 64 rows (vh|vl) x 8 segs
            CP_ASYNC16(vdst + (f * 72 + seg * 8) * 2, vs + (size_t)f * (N_ * 2) + seg * 16);
        }
        CP_COMMIT();
    };

    stage(0, 0);

    for (int kt = 0; kt < 16; kt++) {
        const int buf = kt & 1;
        CP_WAIT0();
        __syncthreads();
        if (kt < 15) stage(kt + 1, buf ^ 1);

        const u32 kbase = ks0 + buf * KSB;
        const u32 vbase = vt0 + buf * VTB;

        #pragma unroll
        for (int kc = 0; kc < 4; kc++) {
            // ---- QK^T for 16 keys (fp16, K-ext 64, 4 ksteps) ----
            float c[2][4];
            c[0][0] = c[0][1] = c[0][2] = c[0][3] = 0.f;
            c[1][0] = c[1][1] = c[1][2] = c[1][3] = 0.f;
            #pragma unroll
            for (int ks = 0; ks < 4; ks++) {
                u32 b00, b01, b10, b11;
                LDSM_X4(b00, b01, b10, b11,
                        kbase + lmK + (u32)((kc * 16 * 72 + 16 * ks) * 2));
                MMAF16(c[0][0], c[0][1], c[0][2], c[0][3],
                       aQ[ks][0], aQ[ks][1], aQ[ks][2], aQ[ks][3], b00, b01);
                MMAF16(c[1][0], c[1][1], c[1][2], c[1][3],
                       aQ[ks][0], aQ[ks][1], aQ[ks][2], aQ[ks][3], b10, b11);
            }

            // ---- softmax slice (fp16 bias pre-scaled by log2e) ----
            int kg = kt * 64 + kc * 16 + fc2;
            float2 bb0 = __half22float2(*(const __half2*)(bias0 + kg));
            float2 bb1 = __half22float2(*(const __half2*)(bias1 + kg));
            float2 bb2 = __half22float2(*(const __half2*)(bias0 + kg + 8));
            float2 bb3 = __half22float2(*(const __half2*)(bias1 + kg + 8));
            float pv0 = ex2(fmaf(c[0][0], sl2e, bb0.x));
            float pv1 = ex2(fmaf(c[0][1], sl2e, bb0.y));
            float pv2 = ex2(fmaf(c[0][2], sl2e, bb1.x));
            float pv3 = ex2(fmaf(c[0][3], sl2e, bb1.y));
            float pw0 = ex2(fmaf(c[1][0], sl2e, bb2.x));
            float pw1 = ex2(fmaf(c[1][1], sl2e, bb2.y));
            float pw2 = ex2(fmaf(c[1][2], sl2e, bb3.x));
            float pw3 = ex2(fmaf(c[1][3], sl2e, bb3.y));
            s0 += (pv0 + pv1) + (pw0 + pw1);
            s1 += (pv2 + pv3) + (pw2 + pw3);

            // P split in bf16 (R14 proven PV path)
            u32 aPh[4], aPl[4];
            split2(pv0, pv1, aPh[0], aPl[0]);
            split2(pv2, pv3, aPh[1], aPl[1]);
            split2(pw0, pw1, aPh[2], aPl[2]);
            split2(pw2, pw3, aPh[3], aPl[3]);

            // ---- P·V (bf16 3-term): ph*vh + pl*vh + ph*vl ----
            #pragma unroll
            for (int nt = 0; nt < 4; nt++) {
                u32 bh0, bh1, bl0, bl1;
                LDSM_X4(bh0, bh1, bl0, bl1,
                        vbase + lmV + (u32)((nt * 8 * 72 + 16 * kc) * 2));
                MMA16816(o[nt][0], o[nt][1], o[nt][2], o[nt][3],
                         aPh[0], aPh[1], aPh[2], aPh[3], bh0, bh1);
                MMA16816(o[nt][0], o[nt][1], o[nt][2], o[nt][3],
                         aPl[0], aPl[1], aPl[2], aPl[3], bh0, bh1);
                MMA16816(o[nt][0], o[nt][1], o[nt][2], o[nt][3],
                         aPh[0], aPh[1], aPh[2], aPh[3], bl0, bl1);
            }
        }
    }

    s0 += __shfl_xor_sync(0xffffffffu, s0, 1);
    s0 += __shfl_xor_sync(0xffffffffu, s0, 2);
    s1 += __shfl_xor_sync(0xffffffffu, s1, 1);
    s1 += __shfl_xor_sync(0xffffffffu, s1, 2);
    float i0 = 1.f / s0, i1 = 1.f / s1;

    #pragma unroll
    for (int nt = 0; nt < 4; nt++) {
        int dd = nt * 8 + fc2;
        float2 w0 = make_float2(o[nt][0] * i0, o[nt][1] * i0);
        float2 w1 = make_float2(o[nt][2] * i1, o[nt][3] * i1);
        *(float2*)&g_o[((size_t)bh * N_ + qr) * HD_ + dd]     = w0;
        *(float2*)&g_o[((size_t)bh * N_ + qr + 8) * HD_ + dd] = w1;
    }
}

// ============================================================
// K_osplit: g_o [bh][tok][d] -> channel-major bf16 splits.
// (launch index 7)
// ============================================================
__global__ void __launch_bounds__(256) osplit_kernel()
{
    __shared__ float ts[32][130];
    const int tid = threadIdx.x;
    const int chunk = blockIdx.x, bh = blockIdx.y;
    const int b = bh >> 3, h = bh & 7;
    const int tok0 = chunk * 128;
    const float* src = g_o + ((size_t)(bh * 1024 + tok0)) * 32;

    #pragma unroll
    for (int r = 0; r < 4; r++) {
        int idx = r * 256 + tid;
        int tok = idx >> 3, d4 = (idx & 7) * 4;
        float4 v = *(const float4*)&src[tok * 32 + d4];
        ts[d4][tok] = v.x; ts[d4+1][tok] = v.y; ts[d4+2][tok] = v.z; ts[d4+3][tok] = v.w;
    }
    __syncthreads();

    const int d = tid >> 3, seg = tid & 7;
    u32 hh[8], ll[8];
    #pragma unroll
    for (int i = 0; i < 8; i++) {
        float v0 = ts[d][seg * 16 + 2*i];
        float v1 = ts[d][seg * 16 + 2*i + 1];
        split2(v0, v1, hh[i], ll[i]);
    }
    size_t off = ((size_t)(b * 256 + h * 32 + d) << 10) + tok0 + seg * 16;
    *(uint4*)&g_osh[off]     = make_uint4(hh[0], hh[1], hh[2], hh[3]);
    *(uint4*)&g_osh[off + 8] = make_uint4(hh[4], hh[5], hh[6], hh[7]);
    *(uint4*)&g_osl[off]     = make_uint4(ll[0], ll[1], ll[2], ll[3]);
    *(uint4*)&g_osl[off + 8] = make_uint4(ll[4], ll[5], ll[6], ll[7]);
}

// ============================================================
// K_projgemm: output projection, 64-token tiles. (launch index 8)
// ============================================================
__global__ void __launch_bounds__(256) projgemm_kernel(
    const float* __restrict__ p1b, const float* __restrict__ p2b,
    float* __restrict__ out)
{
    __shared__ __align__(16) __nv_bfloat16 xh_s[128][72];
    __shared__ __align__(16) __nv_bfloat16 xl_s[128][72];

    const int tid  = threadIdx.x;
    const int lane = tid & 31;
    const int w    = tid >> 5;
    const int b    = blockIdx.y;
    const int tok0 = blockIdx.x * 64;
    const int r0   = w * 16 + (lane >> 2);
    const int fc2  = 2 * (lane & 3);

    const u32 xh0 = smem_u32(&xh_s[0][0]);
    const u32 xl0 = smem_u32(&xl_s[0][0]);
    const u32 lmoff = (u32)((((lane & 7) + ((lane >> 3) & 1) * 8) * 144)
                            + ((lane >> 4) & 1) * 16);

    const float* Bss[2] = {p1b, p2b};

    for (int half = 0; half < 2; half++) {
        __syncthreads();
        {
            const char* sh = (const char*)g_osh
                + (((size_t)(b * 256 + half * 128) << 10) + tok0) * 2;
            const char* sl = (const char*)g_osl
                + (((size_t)(b * 256 + half * 128) << 10) + tok0) * 2;
            #pragma unroll
            for (int r = 0; r < 4; r++) {
                int idx = r * 256 + tid;
                int ch = idx >> 3, seg = idx & 7;
                CP_ASYNC16(xh0 + (ch * 72 + seg * 8) * 2, sh + ((size_t)ch << 11) + seg * 16);
                CP_ASYNC16(xl0 + (ch * 72 + seg * 8) * 2, sl + ((size_t)ch << 11) + seg * 16);
            }
            CP_COMMIT(); CP_WAIT0();
        }
        __syncthreads();

        const int m = 6 + half;
        const uint4* wf = (const uint4*)g_wfrag + ((size_t)(m * 8 + w) * 24) * 32 + lane;

        float c[8][4];
        #pragma unroll
        for (int i = 0; i < 8; i++) { c[i][0] = c[i][1] = c[i][2] = c[i][3] = 0.f; }

        #pragma unroll 4
        for (int ks = 0; ks < 24; ks++) {
            uint4 aa = __ldg(&wf[ks * 32]);
            u32 bb = ((ks < 16) ? xh0 : xl0) + (u32)((ks & 7) * 16 * 144) + lmoff;
            #pragma unroll
            for (int nt = 0; nt < 4; nt++) {
                u32 f0, f1, f2, f3;
                LDSM_X4_T(f0, f1, f2, f3, bb + nt * 32);
                MMA16816(c[2*nt][0], c[2*nt][1], c[2*nt][2], c[2*nt][3],
                         aa.x, aa.y, aa.z, aa.w, f0, f1);
                MMA16816(c[2*nt+1][0], c[2*nt+1][1], c[2*nt+1][2], c[2*nt+1][3],
                         aa.x, aa.y, aa.z, aa.w, f2, f3);
            }
        }

        float bb0 = __ldg(&Bss[half][r0]);
        float bb1 = __ldg(&Bss[half][r0 + 8]);
        float* op = out + ((size_t)(b * 256 + half * 128) << 10);
        #pragma unroll
        for (int n8 = 0; n8 < 8; n8++) {
            int tok = tok0 + n8 * 8 + fc2;
            float2 o0 = make_float2(c[n8][0] + bb0, c[n8][1] + bb0);
            float2 o1 = make_float2(c[n8][2] + bb1, c[n8][3] + bb1);
            *(float2*)&op[((size_t)r0 << 10) + tok] = o0;
            *(float2*)&op[((size_t)(r0 + 8) << 10) + tok] = o1;
        }
    }
}

// ============================================================
extern "C" void kernel_launch(void* const* d_in, const int* in_sizes, int n_in,
                              void* d_out, int out_size)
{
    const float* x    = (const float*)d_in[0];
    const float* q1w  = (const float*)d_in[1];
    const float* q1b  = (const float*)d_in[2];
    const float* q2w  = (const float*)d_in[3];
    const float* q2b  = (const float*)d_in[4];
    const float* k1w  = (const float*)d_in[5];
    const float* k1b  = (const float*)d_in[6];
    const float* k2w  = (const float*)d_in[7];
    const float* k2b  = (const float*)d_in[8];
    const float* v1w  = (const float*)d_in[9];
    const float* v1b  = (const float*)d_in[10];
    const float* v2w  = (const float*)d_in[11];
    const float* v2b  = (const float*)d_in[12];
    const float* p1w  = (const float*)d_in[13];
    const float* p1b  = (const float*)d_in[14];
    const float* p2w  = (const float*)d_in[15];
    const float* p2b  = (const float*)d_in[16];
    const float* ls   = (const float*)d_in[17];
    const float* m1w  = (const float*)d_in[18];
    const float* m1b  = (const float*)d_in[19];
    const float* m2w  = (const float*)d_in[20];
    float* out = (float*)d_out;

    // qkvgemm sits at app-launch index 3 (the ncu slot).
    wext_kernel<<<768, 256>>>(q1w, q2w, k1w, k2w, v1w, v2w, p1w, p2w);
    tab_kernel<<<(TABN_ + 255) / 256, 256>>>(m1w, m1b, m2w);
    bias_kernel<<<dim3(N_, N_ / 256), 256>>>(ls);
    qkvgemm_kernel<<<dim3(16, 16), 256>>>(x, q1b, q2b, k1b, k2b, v1b, v2b);
    normsplit_kernel<<<dim3(8, 128, 2), 128>>>();
    vsplit_kernel<<<4096, 256>>>();
    attn_kernel<<<dim3(N_ / 128, BH_), 256>>>(ls);
    osplit_kernel<<<dim3(8, 128), 256>>>();
    projgemm_kernel<<<dim3(16, 16), 256>>>(p1b, p2b, out);
}